// round 1
// baseline (speedup 1.0000x reference)
#include <cuda_runtime.h>
#include <cuda_bf16.h>
#include <cstdint>
#include <cstddef>

#define NB 1024
#define NT 64
#define NF 121
#define NH 512
#define NSEG 32
#define NG 2048   // 4*H

// ---------------- scratch (device globals; no allocation) ----------------
__device__ float          g_Z   [(size_t)NB * NT * NG];    // 512MB precomputed z / gemm out
__device__ __nv_bfloat16  g_Xhi [(size_t)NB * NT * 128];   // x split, K padded 121->128
__device__ __nv_bfloat16  g_Xlo [(size_t)NB * NT * 128];
__device__ __nv_bfloat16  g_Yhi [(size_t)NB * NT * NH];    // y0 (encoder L0 out) / d0 reuse
__device__ __nv_bfloat16  g_Ylo [(size_t)NB * NT * NH];
__device__ float          g_D1  [(size_t)NB * NSEG * NH];  // decoder L1 outputs (fp32)
__device__ __nv_bfloat16  g_hA_hi[2][NB * NH];             // ping-pong h for layer chain A (enc0->dec0)
__device__ __nv_bfloat16  g_hA_lo[2][NB * NH];
__device__ __nv_bfloat16  g_hB_hi[2][NB * NH];             // chain B (enc1->dec1)
__device__ __nv_bfloat16  g_hB_lo[2][NB * NH];
__device__ float          g_cA  [NB * NH];
__device__ float          g_cB  [NB * NH];
// weight arena: rows of 2048 (interleaved cols), bf16 hi/lo
//   eW0:128 rows @0, eU0:512 @128, eW1:512 @640, eU1:512 @1152,
//   dU0:512 @1664, dW1:512 @2176, dU1:512 @2688   => 3200 rows
__device__ __nv_bfloat16  g_Whi [(size_t)3200 * NG];
__device__ __nv_bfloat16  g_Wlo [(size_t)3200 * NG];
__device__ float          g_bias[4 * NG];                  // eb0,eb1,db0,db1 (interleaved)

// ---------------- helpers ----------------
__device__ __forceinline__ void split2(float v, __nv_bfloat16& hi, __nv_bfloat16& lo) {
    hi = __float2bfloat16(v);
    lo = __float2bfloat16(v - __bfloat162float(hi));
}
__device__ __forceinline__ float sigf(float x) { return 1.0f / (1.0f + __expf(-x)); }

__device__ __forceinline__ void mma16816(float* d, const unsigned* a, unsigned b0, unsigned b1) {
    asm volatile(
        "mma.sync.aligned.m16n8k16.row.col.f32.bf16.bf16.f32 "
        "{%0,%1,%2,%3}, {%4,%5,%6,%7}, {%8,%9}, {%0,%1,%2,%3};"
        : "+f"(d[0]), "+f"(d[1]), "+f"(d[2]), "+f"(d[3])
        : "r"(a[0]), "r"(a[1]), "r"(a[2]), "r"(a[3]), "r"(b0), "r"(b1));
}

// ---------------- prep kernels ----------------
// weight: src [K][2048] natural cols -> arena [Kpad][2048] interleaved cols (cil = (n%512)*4 + n/512)
__global__ void k_split_weight(const float* __restrict__ src, int K, int Kpad,
                               __nv_bfloat16* __restrict__ dhi, __nv_bfloat16* __restrict__ dlo) {
    int idx = blockIdx.x * blockDim.x + threadIdx.x;
    if (idx >= Kpad * NG) return;
    int k = idx / NG, n = idx % NG;
    float v = (k < K) ? src[(size_t)k * NG + n] : 0.0f;
    int cil = (n & 511) * 4 + (n >> 9);
    __nv_bfloat16 hi, lo; split2(v, hi, lo);
    dhi[(size_t)k * NG + cil] = hi;
    dlo[(size_t)k * NG + cil] = lo;
}

__global__ void k_split_bias(const float* __restrict__ src, float* __restrict__ dst) {
    int n = blockIdx.x * blockDim.x + threadIdx.x;
    if (n >= NG) return;
    dst[(n & 511) * 4 + (n >> 9)] = src[n];
}

// x [B][T][F] -> Xhi/Xlo [B*T][128] (zero-padded K)
__global__ void k_split_x(const float* __restrict__ x) {
    int idx = blockIdx.x * blockDim.x + threadIdx.x;
    if (idx >= NB * NT * 128) return;
    int r = idx >> 7, k = idx & 127;
    float v = (k < NF) ? x[(size_t)r * NF + k] : 0.0f;
    __nv_bfloat16 hi, lo; split2(v, hi, lo);
    g_Xhi[idx] = hi; g_Xlo[idx] = lo;
}

__global__ void k_zero_states() {
    int idx = blockIdx.x * blockDim.x + threadIdx.x;
    if (idx >= NB * NH) return;
    __nv_bfloat16 z = __float2bfloat16(0.0f);
    g_hA_hi[0][idx] = z; g_hA_lo[0][idx] = z;
    g_hB_hi[0][idx] = z; g_hB_lo[0][idx] = z;
    g_cA[idx] = 0.0f;    g_cB[idx] = 0.0f;
}

// ---------------- fused bf16x3 GEMM (+ optional LSTM epilogue) ----------------
// C[M][2048] = (Ahi+Alo)[M][K] @ (Whi+Wlo)[K][2048], fp32 accumulate.
// Tile: BM=64, BN=256 (interleaved gate cols), 256 threads = 8 warps (2x4), warp tile 32x64.
template <bool LSTM>
__global__ __launch_bounds__(256)
void k_gemm(const __nv_bfloat16* __restrict__ Ahi, const __nv_bfloat16* __restrict__ Alo, int lda,
            const __nv_bfloat16* __restrict__ Whi, const __nv_bfloat16* __restrict__ Wlo, int K,
            float* __restrict__ outZ,
            const float* __restrict__ pre, long long preStride,
            const float* __restrict__ bias,
            float* __restrict__ cState,
            __nv_bfloat16* __restrict__ hOutHi, __nv_bfloat16* __restrict__ hOutLo,
            __nv_bfloat16* __restrict__ yHi, __nv_bfloat16* __restrict__ yLo,
            long long yStride, float* __restrict__ yF32) {
    __shared__ __align__(16) __nv_bfloat16 sA[2][64][40];   // [hi/lo][m][k], padded
    __shared__ __align__(16) unsigned      sB[2][16][264];  // [hi/lo][k2][c], k-pairs packed, padded

    const int tid = threadIdx.x, lane = tid & 31, warp = tid >> 5;
    const int wm = warp >> 2, wn = warp & 3;
    const int bm = blockIdx.x * 64;
    const int bn = blockIdx.y * 256;

    float acc[2][8][4];
#pragma unroll
    for (int a = 0; a < 2; a++)
#pragma unroll
        for (int b = 0; b < 8; b++)
#pragma unroll
            for (int c = 0; c < 4; c++) acc[a][b][c] = 0.0f;

    for (int kb = 0; kb < K; kb += 32) {
        __syncthreads();
        {   // A tile: 64 rows x 32 k, hi+lo
            int r = tid >> 2, seg = tid & 3;
            *(uint4*)&sA[0][r][seg * 8] = *(const uint4*)(Ahi + (size_t)(bm + r) * lda + kb + seg * 8);
            *(uint4*)&sA[1][r][seg * 8] = *(const uint4*)(Alo + (size_t)(bm + r) * lda + kb + seg * 8);
        }
#pragma unroll
        for (int hl = 0; hl < 2; hl++) {  // B tile: 32 k x 256 c, packed k-pairs
            const __nv_bfloat16* Wp = hl ? Wlo : Whi;
#pragma unroll
            for (int it = 0; it < 2; it++) {
                int idx = it * 256 + tid;
                int k2 = idx >> 5, c8 = (idx & 31) << 3;
                uint4 r0 = *(const uint4*)(Wp + (size_t)(kb + k2 * 2) * NG + bn + c8);
                uint4 r1 = *(const uint4*)(Wp + (size_t)(kb + k2 * 2 + 1) * NG + bn + c8);
                const unsigned short* e0 = (const unsigned short*)&r0;
                const unsigned short* e1 = (const unsigned short*)&r1;
#pragma unroll
                for (int j = 0; j < 8; j++)
                    sB[hl][k2][c8 + j] = (unsigned)e0[j] | ((unsigned)e1[j] << 16);
            }
        }
        __syncthreads();
#pragma unroll
        for (int kk = 0; kk < 2; kk++) {  // two k16 halves per chunk
            const int k0 = kk * 16;
            unsigned afr[2][2][4];
#pragma unroll
            for (int mt = 0; mt < 2; mt++) {
                int row = wm * 32 + mt * 16 + (lane >> 2);
                int col = k0 + (lane & 3) * 2;
#pragma unroll
                for (int hl = 0; hl < 2; hl++) {
                    afr[hl][mt][0] = *(const unsigned*)&sA[hl][row][col];
                    afr[hl][mt][1] = *(const unsigned*)&sA[hl][row + 8][col];
                    afr[hl][mt][2] = *(const unsigned*)&sA[hl][row][col + 8];
                    afr[hl][mt][3] = *(const unsigned*)&sA[hl][row + 8][col + 8];
                }
            }
#pragma unroll
            for (int jt = 0; jt < 8; jt++) {
                int c = wn * 64 + jt * 8 + (lane >> 2);
                int kq = kk * 8 + (lane & 3);
                unsigned bh0 = sB[0][kq][c], bh1 = sB[0][kq + 4][c];
                unsigned bl0 = sB[1][kq][c], bl1 = sB[1][kq + 4][c];
#pragma unroll
                for (int mt = 0; mt < 2; mt++) {
                    mma16816(acc[mt][jt], afr[0][mt], bh0, bh1);  // Ahi*Bhi
                    mma16816(acc[mt][jt], afr[0][mt], bl0, bl1);  // Ahi*Blo
                    mma16816(acc[mt][jt], afr[1][mt], bh0, bh1);  // Alo*Bhi
                }
            }
        }
    }

    if (!LSTM) {
#pragma unroll
        for (int mt = 0; mt < 2; mt++) {
            int r = bm + wm * 32 + mt * 16 + (lane >> 2);
#pragma unroll
            for (int jt = 0; jt < 8; jt++) {
                int c = bn + wn * 64 + jt * 8 + (lane & 3) * 2;
                float* o = outZ + (size_t)r * NG + c;
                o[0] = acc[mt][jt][0]; o[1] = acc[mt][jt][1];
                o += (size_t)8 * NG;
                o[0] = acc[mt][jt][2]; o[1] = acc[mt][jt][3];
            }
        }
    } else {
#pragma unroll
        for (int mt = 0; mt < 2; mt++) {
            int rA = bm + wm * 32 + mt * 16 + (lane >> 2);
            int rB = rA + 8;
#pragma unroll
            for (int jt = 0; jt < 8; jt++) {
                int c = bn + wn * 64 + jt * 8 + (lane & 3) * 2;
                float z0 = acc[mt][jt][0] + bias[c];
                float z1 = acc[mt][jt][1] + bias[c + 1];
                float z2 = acc[mt][jt][2] + bias[c];
                float z3 = acc[mt][jt][3] + bias[c + 1];
                if (pre) {
                    z0 += pre[(size_t)rA * preStride + c];
                    z1 += pre[(size_t)rA * preStride + c + 1];
                    z2 += pre[(size_t)rB * preStride + c];
                    z3 += pre[(size_t)rB * preStride + c + 1];
                }
                // partner lane holds the other two gates of the same (row, j)
                float p0 = __shfl_xor_sync(0xffffffffu, z0, 1);
                float p1 = __shfl_xor_sync(0xffffffffu, z1, 1);
                float p2 = __shfl_xor_sync(0xffffffffu, z2, 1);
                float p3 = __shfl_xor_sync(0xffffffffu, z3, 1);
                if (!(lane & 1)) {   // even lanes hold (i,f), received (g,o)
                    int j = c >> 2;
#pragma unroll
                    for (int rr = 0; rr < 2; rr++) {
                        int r = rr ? rB : rA;
                        float zi = rr ? z2 : z0, zf = rr ? z3 : z1;
                        float zg = rr ? p2 : p0, zo = rr ? p3 : p1;
                        float ig = sigf(zi), fg = sigf(zf);
                        float gg = tanhf(zg), og = sigf(zo);
                        size_t si = (size_t)r * NH + j;
                        float cn = fg * cState[si] + ig * gg;
                        float h = og * tanhf(cn);
                        cState[si] = cn;
                        __nv_bfloat16 hh, hl; split2(h, hh, hl);
                        hOutHi[si] = hh; hOutLo[si] = hl;
                        if (yHi) {
                            size_t yi = (size_t)r * yStride + j;
                            yHi[yi] = hh; yLo[yi] = hl;
                        }
                        if (yF32) yF32[(size_t)r * yStride + j] = h;
                    }
                }
            }
        }
    }
}

// ---------------- final dense: out[r] = D1[r] . denseW + denseb ----------------
__global__ void k_dense(const float* __restrict__ w, const float* __restrict__ b,
                        float* __restrict__ out) {
    int r = blockIdx.x * 8 + (threadIdx.x >> 5);
    int lane = threadIdx.x & 31;
    const float* row = g_D1 + (size_t)r * NH;
    float s = 0.0f;
#pragma unroll
    for (int k = lane; k < NH; k += 32) s += row[k] * w[k];
#pragma unroll
    for (int o = 16; o; o >>= 1) s += __shfl_xor_sync(0xffffffffu, s, o);
    if (lane == 0) out[r] = s + b[0];
}

// ---------------- host ----------------
extern "C" void kernel_launch(void* const* d_in, const int* in_sizes, int n_in,
                              void* d_out, int out_size) {
    (void)in_sizes; (void)n_in; (void)out_size;
    const float* x      = (const float*)d_in[0];
    const float* eW0    = (const float*)d_in[2];
    const float* eU0    = (const float*)d_in[3];
    const float* eb0    = (const float*)d_in[4];
    const float* eW1    = (const float*)d_in[5];
    const float* eU1    = (const float*)d_in[6];
    const float* eb1    = (const float*)d_in[7];
    const float* dU0    = (const float*)d_in[9];
    const float* db0    = (const float*)d_in[10];
    const float* dW1    = (const float*)d_in[11];
    const float* dU1    = (const float*)d_in[12];
    const float* db1    = (const float*)d_in[13];
    const float* denseW = (const float*)d_in[14];
    const float* denseb = (const float*)d_in[15];

    void *pZ, *pXhi, *pXlo, *pYhi, *pYlo, *pD1, *pAh, *pAl, *pBh, *pBl, *pCA, *pCB, *pWh, *pWl, *pBs;
    cudaGetSymbolAddress(&pZ, g_Z);
    cudaGetSymbolAddress(&pXhi, g_Xhi);  cudaGetSymbolAddress(&pXlo, g_Xlo);
    cudaGetSymbolAddress(&pYhi, g_Yhi);  cudaGetSymbolAddress(&pYlo, g_Ylo);
    cudaGetSymbolAddress(&pD1, g_D1);
    cudaGetSymbolAddress(&pAh, g_hA_hi); cudaGetSymbolAddress(&pAl, g_hA_lo);
    cudaGetSymbolAddress(&pBh, g_hB_hi); cudaGetSymbolAddress(&pBl, g_hB_lo);
    cudaGetSymbolAddress(&pCA, g_cA);    cudaGetSymbolAddress(&pCB, g_cB);
    cudaGetSymbolAddress(&pWh, g_Whi);   cudaGetSymbolAddress(&pWl, g_Wlo);
    cudaGetSymbolAddress(&pBs, g_bias);

    float* Z = (float*)pZ;
    __nv_bfloat16* Xhi = (__nv_bfloat16*)pXhi; __nv_bfloat16* Xlo = (__nv_bfloat16*)pXlo;
    __nv_bfloat16* Yhi = (__nv_bfloat16*)pYhi; __nv_bfloat16* Ylo = (__nv_bfloat16*)pYlo;
    float* D1 = (float*)pD1;
    __nv_bfloat16* hAhi[2] = {(__nv_bfloat16*)pAh, (__nv_bfloat16*)pAh + NB * NH};
    __nv_bfloat16* hAlo[2] = {(__nv_bfloat16*)pAl, (__nv_bfloat16*)pAl + NB * NH};
    __nv_bfloat16* hBhi[2] = {(__nv_bfloat16*)pBh, (__nv_bfloat16*)pBh + NB * NH};
    __nv_bfloat16* hBlo[2] = {(__nv_bfloat16*)pBl, (__nv_bfloat16*)pBl + NB * NH};
    float* cA = (float*)pCA; float* cB = (float*)pCB;
    __nv_bfloat16* Whi = (__nv_bfloat16*)pWh; __nv_bfloat16* Wlo = (__nv_bfloat16*)pWl;
    float* Bias = (float*)pBs;

    const int R_eW0 = 0, R_eU0 = 128, R_eW1 = 640, R_eU1 = 1152, R_dU0 = 1664, R_dW1 = 2176, R_dU1 = 2688;

    // --- prep ---
    auto sw = [&](const float* src, int K, int Kpad, int off) {
        int n = Kpad * NG;
        k_split_weight<<<(n + 255) / 256, 256>>>(src, K, Kpad,
            Whi + (size_t)off * NG, Wlo + (size_t)off * NG);
    };
    sw(eW0, NF, 128, R_eW0);
    sw(eU0, NH, NH, R_eU0);
    sw(eW1, NH, NH, R_eW1);
    sw(eU1, NH, NH, R_eU1);
    sw(dU0, NH, NH, R_dU0);
    sw(dW1, NH, NH, R_dW1);
    sw(dU1, NH, NH, R_dU1);
    k_split_bias<<<8, 256>>>(eb0, Bias + 0 * NG);
    k_split_bias<<<8, 256>>>(eb1, Bias + 1 * NG);
    k_split_bias<<<8, 256>>>(db0, Bias + 2 * NG);
    k_split_bias<<<8, 256>>>(db1, Bias + 3 * NG);
    k_split_x<<<(NB * NT * 128) / 256, 256>>>(x);
    k_zero_states<<<(NB * NH) / 256, 256>>>();

    const dim3 blk(256);
    const dim3 gStep(NB / 64, 8);

    // --- encoder L0: precompute x@eW0, then 64 recurrent steps ---
    k_gemm<false><<<dim3(NB * NT / 64, 8), blk>>>(Xhi, Xlo, 128,
        Whi + (size_t)R_eW0 * NG, Wlo + (size_t)R_eW0 * NG, 128, Z,
        nullptr, 0, nullptr, nullptr, nullptr, nullptr, nullptr, nullptr, 0, nullptr);
    for (int t = 0; t < NT; t++) {
        k_gemm<true><<<gStep, blk>>>(hAhi[t & 1], hAlo[t & 1], NH,
            Whi + (size_t)R_eU0 * NG, Wlo + (size_t)R_eU0 * NG, NH, nullptr,
            Z + (size_t)t * NG, (long long)NT * NG, Bias + 0 * NG, cA,
            hAhi[(t + 1) & 1], hAlo[(t + 1) & 1],
            Yhi + (size_t)t * NH, Ylo + (size_t)t * NH, (long long)NT * NH, nullptr);
    }
    // --- encoder L1: precompute y0@eW1, then 64 steps ---
    k_gemm<false><<<dim3(NB * NT / 64, 8), blk>>>(Yhi, Ylo, NH,
        Whi + (size_t)R_eW1 * NG, Wlo + (size_t)R_eW1 * NG, NH, Z,
        nullptr, 0, nullptr, nullptr, nullptr, nullptr, nullptr, nullptr, 0, nullptr);
    for (int t = 0; t < NT; t++) {
        k_gemm<true><<<gStep, blk>>>(hBhi[t & 1], hBlo[t & 1], NH,
            Whi + (size_t)R_eU1 * NG, Wlo + (size_t)R_eU1 * NG, NH, nullptr,
            Z + (size_t)t * NG, (long long)NT * NG, Bias + 1 * NG, cB,
            hBhi[(t + 1) & 1], hBlo[(t + 1) & 1],
            nullptr, nullptr, 0, nullptr);
    }
    // --- decoder L0: input is zeros; continues from enc-L0 final state (in buf[0]/cA) ---
    for (int t = 0; t < NSEG; t++) {
        k_gemm<true><<<gStep, blk>>>(hAhi[t & 1], hAlo[t & 1], NH,
            Whi + (size_t)R_dU0 * NG, Wlo + (size_t)R_dU0 * NG, NH, nullptr,
            nullptr, 0, Bias + 2 * NG, cA,
            hAhi[(t + 1) & 1], hAlo[(t + 1) & 1],
            Yhi + (size_t)t * NH, Ylo + (size_t)t * NH, (long long)NSEG * NH, nullptr);
    }
    // --- decoder L1: precompute d0@dW1, then 32 steps, emit fp32 d1 ---
    k_gemm<false><<<dim3(NB * NSEG / 64, 8), blk>>>(Yhi, Ylo, NH,
        Whi + (size_t)R_dW1 * NG, Wlo + (size_t)R_dW1 * NG, NH, Z,
        nullptr, 0, nullptr, nullptr, nullptr, nullptr, nullptr, nullptr, 0, nullptr);
    for (int t = 0; t < NSEG; t++) {
        k_gemm<true><<<gStep, blk>>>(hBhi[t & 1], hBlo[t & 1], NH,
            Whi + (size_t)R_dU1 * NG, Wlo + (size_t)R_dU1 * NG, NH, nullptr,
            Z + (size_t)t * NG, (long long)NSEG * NG, Bias + 3 * NG, cB,
            hBhi[(t + 1) & 1], hBlo[(t + 1) & 1],
            nullptr, nullptr, (long long)NSEG * NH, D1 + (size_t)t * NH);
    }
    // --- final dense ---
    k_dense<<<NB * NSEG / 8, 256>>>(denseW, denseb, (float*)d_out);
}

// round 3
// speedup vs baseline: 1.2136x; 1.2136x over previous
#include <cuda_runtime.h>
#include <cuda_bf16.h>
#include <cstdint>
#include <cstddef>

#define NB 1024
#define NT 64
#define NF 121
#define NH 512
#define NSEG 32
#define NG 2048   // 4*H

// ---------------- scratch (device globals; no allocation) ----------------
__device__ __align__(16) float          g_Z   [(size_t)NB * NT * NG];    // precomputed z (interleaved cols)
__device__ __align__(16) __nv_bfloat16  g_Xhi [(size_t)NB * NT * 128];   // x split, K padded 121->128
__device__ __align__(16) __nv_bfloat16  g_Xlo [(size_t)NB * NT * 128];
__device__ __align__(16) __nv_bfloat16  g_Yhi [(size_t)NB * NT * NH];    // y0 / d0 staging
__device__ __align__(16) __nv_bfloat16  g_Ylo [(size_t)NB * NT * NH];
__device__ __align__(16) float          g_D1  [(size_t)NB * NSEG * NH];  // decoder L1 outputs
__device__ __align__(16) __nv_bfloat16  g_hA_hi[2][NB * NH];
__device__ __align__(16) __nv_bfloat16  g_hA_lo[2][NB * NH];
__device__ __align__(16) __nv_bfloat16  g_hB_hi[2][NB * NH];
__device__ __align__(16) __nv_bfloat16  g_hB_lo[2][NB * NH];
__device__ __align__(16) float          g_cA  [NB * NH];
__device__ __align__(16) float          g_cB  [NB * NH];
// weight arena: W^T, rows = interleaved out-col (j*4+gate), K contiguous.
#define O_eW0 0
#define O_eU0 (2048*128)
#define O_eW1 (O_eU0 + 2048*512)
#define O_eU1 (O_eW1 + 2048*512)
#define O_dU0 (O_eU1 + 2048*512)
#define O_dW1 (O_dU0 + 2048*512)
#define O_dU1 (O_dW1 + 2048*512)
#define W_TOTAL (O_dU1 + 2048*512)
__device__ __align__(16) __nv_bfloat16  g_WhiT[W_TOTAL];
__device__ __align__(16) __nv_bfloat16  g_WloT[W_TOTAL];
__device__ __align__(16) float          g_bias[4 * NG];   // eb0,eb1,db0,db1 (interleaved)

// ---------------- helpers ----------------
__device__ __forceinline__ void split2(float v, __nv_bfloat16& hi, __nv_bfloat16& lo) {
    hi = __float2bfloat16(v);
    lo = __float2bfloat16(v - __bfloat162float(hi));
}
__device__ __forceinline__ float sigf(float x) { return 1.0f / (1.0f + __expf(-x)); }

__device__ __forceinline__ uint32_t smem_u32(const void* p) {
    uint32_t a;
    asm("{ .reg .u64 t; cvta.to.shared.u64 t, %1; cvt.u32.u64 %0, t; }" : "=r"(a) : "l"(p));
    return a;
}
__device__ __forceinline__ void mma16816(float* d, const unsigned* a, unsigned b0, unsigned b1) {
    asm volatile(
        "mma.sync.aligned.m16n8k16.row.col.f32.bf16.bf16.f32 "
        "{%0,%1,%2,%3}, {%4,%5,%6,%7}, {%8,%9}, {%0,%1,%2,%3};"
        : "+f"(d[0]), "+f"(d[1]), "+f"(d[2]), "+f"(d[3])
        : "r"(a[0]), "r"(a[1]), "r"(a[2]), "r"(a[3]), "r"(b0), "r"(b1));
}
__device__ __forceinline__ void ldsm4(uint32_t* r, uint32_t addr) {
    asm volatile("ldmatrix.sync.aligned.m8n8.x4.shared.b16 {%0,%1,%2,%3}, [%4];"
                 : "=r"(r[0]), "=r"(r[1]), "=r"(r[2]), "=r"(r[3]) : "r"(addr));
}
__device__ __forceinline__ void cpa16(uint32_t dst, const void* src) {
    asm volatile("cp.async.cg.shared.global [%0], [%1], 16;" :: "r"(dst), "l"(src));
}
#define CP_COMMIT() asm volatile("cp.async.commit_group;" ::: "memory")

// smem: two 80KB buffers: Ahi 8K | Alo 8K | Bhi 32K | Blo 32K
#define BUF_STRIDE 81920u
#define SMEM_DYN   (2 * 81920)

// ---------------- prep kernels ----------------
// W^T split: src [K][2048] -> dst [cil][Kpad], cil=(n%512)*4 + n/512, K contiguous
__global__ void k_split_weightT(const float* __restrict__ src, int K, int Kpad,
                                __nv_bfloat16* __restrict__ dhi, __nv_bfloat16* __restrict__ dlo) {
    int idx = blockIdx.x * blockDim.x + threadIdx.x;
    if (idx >= 2048 * Kpad) return;
    int n = idx / Kpad, k = idx % Kpad;
    float v = (k < K) ? src[(size_t)k * NG + n] : 0.0f;
    int cil = (n & 511) * 4 + (n >> 9);
    __nv_bfloat16 hi, lo; split2(v, hi, lo);
    dhi[(size_t)cil * Kpad + k] = hi;
    dlo[(size_t)cil * Kpad + k] = lo;
}

__global__ void k_split_bias(const float* __restrict__ src, float* __restrict__ dst) {
    int n = blockIdx.x * blockDim.x + threadIdx.x;
    if (n >= NG) return;
    dst[(n & 511) * 4 + (n >> 9)] = src[n];
}

__global__ void k_split_x(const float* __restrict__ x) {
    int idx = blockIdx.x * blockDim.x + threadIdx.x;
    if (idx >= NB * NT * 128) return;
    int r = idx >> 7, k = idx & 127;
    float v = (k < NF) ? x[(size_t)r * NF + k] : 0.0f;
    __nv_bfloat16 hi, lo; split2(v, hi, lo);
    g_Xhi[idx] = hi; g_Xlo[idx] = lo;
}

__global__ void k_zero_states() {
    int idx = blockIdx.x * blockDim.x + threadIdx.x;
    if (idx >= NB * NH) return;
    __nv_bfloat16 z = __float2bfloat16(0.0f);
    g_hA_hi[0][idx] = z; g_hA_lo[0][idx] = z;
    g_hB_hi[0][idx] = z; g_hB_lo[0][idx] = z;
    g_cA[idx] = 0.0f;    g_cB[idx] = 0.0f;
}

// ---------------- bf16x3 GEMM via mma.sync, cp.async double-buffered ----------------
// C[M][2048] = (Ahi+Alo)[M][K] @ (Bhi+Blo)^T ; B stored [n][k] K-contig.
// Tile BM=64 x BN=256, 256 thr = 8 warps (2x4), warp tile 32x64. K chunks of 64.
template <bool LSTM>
__global__ __launch_bounds__(256)
void k_gemm3(const __nv_bfloat16* __restrict__ Ahi, const __nv_bfloat16* __restrict__ Alo, int lda,
             const __nv_bfloat16* __restrict__ Bhi, const __nv_bfloat16* __restrict__ Blo, int ldw,
             int nc,
             float* __restrict__ outZ,
             const float* __restrict__ pre, long long preStride,
             const float* __restrict__ bias,
             float* __restrict__ cState,
             __nv_bfloat16* __restrict__ hOutHi, __nv_bfloat16* __restrict__ hOutLo,
             __nv_bfloat16* __restrict__ yHi, __nv_bfloat16* __restrict__ yLo,
             long long yStride, float* __restrict__ yF32) {
    extern __shared__ __align__(128) char smem[];
    const uint32_t sb = smem_u32(smem);
    const int tid = threadIdx.x, lane = tid & 31, warp = tid >> 5;
    const int wm = warp >> 2, wn = warp & 3;
    const int bm = blockIdx.x * 64;
    const int bn = blockIdx.y * 256;

    float acc[2][8][4];
#pragma unroll
    for (int a = 0; a < 2; a++)
#pragma unroll
        for (int b = 0; b < 8; b++)
#pragma unroll
            for (int c = 0; c < 4; c++) acc[a][b][c] = 0.0f;

    // per-lane ldmatrix constants
    const uint32_t a_lc = (uint32_t)(lane & 16);            // col +16B for lanes 16-31
    const uint32_t b_lc = (uint32_t)((lane & 8) << 1);      // col +16B for lanes 8-15,24-31
    const int b_r8 = (lane & 16) >> 1;                      // row +8 for lanes 16-31

    auto issue = [&](int c) {
        const int kb = c * 64;
        const uint32_t dbase = sb + (uint32_t)(c & 1) * BUF_STRIDE;
#pragma unroll
        for (int m = 0; m < 2; m++) {                       // A hi/lo: 64 rows x 128B
            const __nv_bfloat16* src = m ? Alo : Ahi;
            const uint32_t db = dbase + (uint32_t)m * 8192u;
#pragma unroll
            for (int it = 0; it < 2; it++) {
                int u = it * 256 + tid;
                int row = u >> 3, seg = u & 7;
                uint32_t off = (uint32_t)(row * 128) + (uint32_t)((seg * 16) ^ ((row & 7) * 16));
                cpa16(db + off, src + (size_t)(bm + row) * lda + kb + seg * 8);
            }
        }
#pragma unroll
        for (int m = 0; m < 2; m++) {                       // B hi/lo: 256 rows x 128B
            const __nv_bfloat16* src = m ? Blo : Bhi;
            const uint32_t db = dbase + 16384u + (uint32_t)m * 32768u;
#pragma unroll
            for (int it = 0; it < 8; it++) {
                int u = it * 256 + tid;
                int row = u >> 3, seg = u & 7;
                uint32_t off = (uint32_t)(row * 128) + (uint32_t)((seg * 16) ^ ((row & 7) * 16));
                cpa16(db + off, src + (size_t)(bn + row) * ldw + kb + seg * 8);
            }
        }
        CP_COMMIT();
    };

    issue(0);
    for (int c = 0; c < nc; ++c) {
        if (c + 1 < nc) {
            issue(c + 1);
            asm volatile("cp.async.wait_group 1;" ::: "memory");
        } else {
            asm volatile("cp.async.wait_group 0;" ::: "memory");
        }
        __syncthreads();
        const uint32_t dbase = sb + (uint32_t)(c & 1) * BUF_STRIDE;
#pragma unroll
        for (int k16 = 0; k16 < 4; ++k16) {
            const uint32_t kcol = (uint32_t)(k16 * 32);
            uint32_t af[2][2][4];
#pragma unroll
            for (int hl = 0; hl < 2; ++hl)
#pragma unroll
                for (int mt = 0; mt < 2; ++mt) {
                    int r = wm * 32 + mt * 16 + (lane & 15);
                    uint32_t addr = dbase + (uint32_t)hl * 8192u + (uint32_t)(r * 128)
                                  + ((kcol + a_lc) ^ (uint32_t)((r & 7) * 16));
                    ldsm4(af[hl][mt], addr);
                }
            uint32_t bfr[2][8][2];
#pragma unroll
            for (int hl = 0; hl < 2; ++hl)
#pragma unroll
                for (int jq = 0; jq < 4; ++jq) {
                    int r = wn * 64 + jq * 16 + (lane & 7) + b_r8;
                    uint32_t addr = dbase + 16384u + (uint32_t)hl * 32768u + (uint32_t)(r * 128)
                                  + ((kcol + b_lc) ^ (uint32_t)((r & 7) * 16));
                    uint32_t t4[4];
                    ldsm4(t4, addr);
                    bfr[hl][jq * 2][0] = t4[0];     bfr[hl][jq * 2][1] = t4[1];
                    bfr[hl][jq * 2 + 1][0] = t4[2]; bfr[hl][jq * 2 + 1][1] = t4[3];
                }
#pragma unroll
            for (int jt = 0; jt < 8; ++jt)
#pragma unroll
                for (int mt = 0; mt < 2; ++mt) {
                    mma16816(acc[mt][jt], af[0][mt], bfr[0][jt][0], bfr[0][jt][1]);  // hi*hi
                    mma16816(acc[mt][jt], af[0][mt], bfr[1][jt][0], bfr[1][jt][1]);  // hi*lo
                    mma16816(acc[mt][jt], af[1][mt], bfr[0][jt][0], bfr[0][jt][1]);  // lo*hi
                }
        }
        __syncthreads();
    }

    // ---------------- epilogue (same as validated round-1) ----------------
    if (!LSTM) {
#pragma unroll
        for (int mt = 0; mt < 2; mt++) {
            int r = bm + wm * 32 + mt * 16 + (lane >> 2);
#pragma unroll
            for (int jt = 0; jt < 8; jt++) {
                int cix = bn + wn * 64 + jt * 8 + (lane & 3) * 2;
                float* o = outZ + (size_t)r * NG + cix;
                o[0] = acc[mt][jt][0]; o[1] = acc[mt][jt][1];
                o += (size_t)8 * NG;
                o[0] = acc[mt][jt][2]; o[1] = acc[mt][jt][3];
            }
        }
    } else {
#pragma unroll
        for (int mt = 0; mt < 2; mt++) {
            int rA = bm + wm * 32 + mt * 16 + (lane >> 2);
            int rB = rA + 8;
#pragma unroll
            for (int jt = 0; jt < 8; jt++) {
                int cix = bn + wn * 64 + jt * 8 + (lane & 3) * 2;
                float z0 = acc[mt][jt][0] + bias[cix];
                float z1 = acc[mt][jt][1] + bias[cix + 1];
                float z2 = acc[mt][jt][2] + bias[cix];
                float z3 = acc[mt][jt][3] + bias[cix + 1];
                if (pre) {
                    z0 += pre[(size_t)rA * preStride + cix];
                    z1 += pre[(size_t)rA * preStride + cix + 1];
                    z2 += pre[(size_t)rB * preStride + cix];
                    z3 += pre[(size_t)rB * preStride + cix + 1];
                }
                float p0 = __shfl_xor_sync(0xffffffffu, z0, 1);
                float p1 = __shfl_xor_sync(0xffffffffu, z1, 1);
                float p2 = __shfl_xor_sync(0xffffffffu, z2, 1);
                float p3 = __shfl_xor_sync(0xffffffffu, z3, 1);
                if (!(lane & 1)) {   // even lanes hold (i,f), received (g,o)
                    int j = cix >> 2;
#pragma unroll
                    for (int rr = 0; rr < 2; rr++) {
                        int r = rr ? rB : rA;
                        float zi = rr ? z2 : z0, zf = rr ? z3 : z1;
                        float zg = rr ? p2 : p0, zo = rr ? p3 : p1;
                        float ig = sigf(zi), fg = sigf(zf);
                        float gg = tanhf(zg), og = sigf(zo);
                        size_t si = (size_t)r * NH + j;
                        float cn = fg * cState[si] + ig * gg;
                        float h = og * tanhf(cn);
                        cState[si] = cn;
                        __nv_bfloat16 hh, hlv; split2(h, hh, hlv);
                        hOutHi[si] = hh; hOutLo[si] = hlv;
                        if (yHi) {
                            size_t yi = (size_t)r * yStride + j;
                            yHi[yi] = hh; yLo[yi] = hlv;
                        }
                        if (yF32) yF32[(size_t)r * yStride + j] = h;
                    }
                }
            }
        }
    }
}

// ---------------- final dense ----------------
__global__ void k_dense(const float* __restrict__ w, const float* __restrict__ b,
                        float* __restrict__ out) {
    int r = blockIdx.x * 8 + (threadIdx.x >> 5);
    int lane = threadIdx.x & 31;
    const float* row = g_D1 + (size_t)r * NH;
    float s = 0.0f;
#pragma unroll
    for (int k = lane; k < NH; k += 32) s += row[k] * w[k];
#pragma unroll
    for (int o = 16; o; o >>= 1) s += __shfl_xor_sync(0xffffffffu, s, o);
    if (lane == 0) out[r] = s + b[0];
}

// ---------------- host ----------------
extern "C" void kernel_launch(void* const* d_in, const int* in_sizes, int n_in,
                              void* d_out, int out_size) {
    (void)in_sizes; (void)n_in; (void)out_size;
    const float* x      = (const float*)d_in[0];
    const float* eW0    = (const float*)d_in[2];
    const float* eU0    = (const float*)d_in[3];
    const float* eb0    = (const float*)d_in[4];
    const float* eW1    = (const float*)d_in[5];
    const float* eU1    = (const float*)d_in[6];
    const float* eb1    = (const float*)d_in[7];
    const float* dU0    = (const float*)d_in[9];
    const float* db0    = (const float*)d_in[10];
    const float* dW1    = (const float*)d_in[11];
    const float* dU1    = (const float*)d_in[12];
    const float* db1    = (const float*)d_in[13];
    const float* denseW = (const float*)d_in[14];
    const float* denseb = (const float*)d_in[15];

    cudaFuncSetAttribute(k_gemm3<true>,  cudaFuncAttributeMaxDynamicSharedMemorySize, SMEM_DYN);
    cudaFuncSetAttribute(k_gemm3<false>, cudaFuncAttributeMaxDynamicSharedMemorySize, SMEM_DYN);

    void *pZ, *pXhi, *pXlo, *pYhi, *pYlo, *pD1, *pAh, *pAl, *pBh, *pBl, *pCA, *pCB, *pWh, *pWl, *pBs;
    cudaGetSymbolAddress(&pZ, g_Z);
    cudaGetSymbolAddress(&pXhi, g_Xhi);  cudaGetSymbolAddress(&pXlo, g_Xlo);
    cudaGetSymbolAddress(&pYhi, g_Yhi);  cudaGetSymbolAddress(&pYlo, g_Ylo);
    cudaGetSymbolAddress(&pD1, g_D1);
    cudaGetSymbolAddress(&pAh, g_hA_hi); cudaGetSymbolAddress(&pAl, g_hA_lo);
    cudaGetSymbolAddress(&pBh, g_hB_hi); cudaGetSymbolAddress(&pBl, g_hB_lo);
    cudaGetSymbolAddress(&pCA, g_cA);    cudaGetSymbolAddress(&pCB, g_cB);
    cudaGetSymbolAddress(&pWh, g_WhiT);  cudaGetSymbolAddress(&pWl, g_WloT);
    cudaGetSymbolAddress(&pBs, g_bias);

    float* Z = (float*)pZ;
    __nv_bfloat16* Xhi = (__nv_bfloat16*)pXhi; __nv_bfloat16* Xlo = (__nv_bfloat16*)pXlo;
    __nv_bfloat16* Yhi = (__nv_bfloat16*)pYhi; __nv_bfloat16* Ylo = (__nv_bfloat16*)pYlo;
    float* D1 = (float*)pD1;
    __nv_bfloat16* hAhi[2] = {(__nv_bfloat16*)pAh, (__nv_bfloat16*)pAh + NB * NH};
    __nv_bfloat16* hAlo[2] = {(__nv_bfloat16*)pAl, (__nv_bfloat16*)pAl + NB * NH};
    __nv_bfloat16* hBhi[2] = {(__nv_bfloat16*)pBh, (__nv_bfloat16*)pBh + NB * NH};
    __nv_bfloat16* hBlo[2] = {(__nv_bfloat16*)pBl, (__nv_bfloat16*)pBl + NB * NH};
    float* cA = (float*)pCA; float* cB = (float*)pCB;
    __nv_bfloat16* Whi = (__nv_bfloat16*)pWh; __nv_bfloat16* Wlo = (__nv_bfloat16*)pWl;
    float* Bias = (float*)pBs;

    // --- prep ---
    auto sw = [&](const float* src, int K, int Kpad, size_t off) {
        int n = 2048 * Kpad;
        k_split_weightT<<<(n + 255) / 256, 256>>>(src, K, Kpad, Whi + off, Wlo + off);
    };
    sw(eW0, NF, 128, O_eW0);
    sw(eU0, NH, NH, O_eU0);
    sw(eW1, NH, NH, O_eW1);
    sw(eU1, NH, NH, O_eU1);
    sw(dU0, NH, NH, O_dU0);
    sw(dW1, NH, NH, O_dW1);
    sw(dU1, NH, NH, O_dU1);
    k_split_bias<<<8, 256>>>(eb0, Bias + 0 * NG);
    k_split_bias<<<8, 256>>>(eb1, Bias + 1 * NG);
    k_split_bias<<<8, 256>>>(db0, Bias + 2 * NG);
    k_split_bias<<<8, 256>>>(db1, Bias + 3 * NG);
    k_split_x<<<(NB * NT * 128) / 256, 256>>>(x);
    k_zero_states<<<(NB * NH) / 256, 256>>>();

    const dim3 blk(256);
    const dim3 gStep(NB / 64, 8);   // (M-blocks, N-blocks) = 128 CTAs

    // --- encoder L0: precompute x@eW0, then 64 recurrent steps ---
    k_gemm3<false><<<dim3(NB * NT / 64, 8), blk, SMEM_DYN>>>(
        Xhi, Xlo, 128, Whi + O_eW0, Wlo + O_eW0, 128, 2, Z,
        nullptr, 0, nullptr, nullptr, nullptr, nullptr, nullptr, nullptr, 0, nullptr);
    for (int t = 0; t < NT; t++) {
        k_gemm3<true><<<gStep, blk, SMEM_DYN>>>(
            hAhi[t & 1], hAlo[t & 1], NH, Whi + O_eU0, Wlo + O_eU0, NH, 8, nullptr,
            Z + (size_t)t * NG, (long long)NT * NG, Bias + 0 * NG, cA,
            hAhi[(t + 1) & 1], hAlo[(t + 1) & 1],
            Yhi + (size_t)t * NH, Ylo + (size_t)t * NH, (long long)NT * NH, nullptr);
    }
    // --- encoder L1: precompute y0@eW1, then 64 steps ---
    k_gemm3<false><<<dim3(NB * NT / 64, 8), blk, SMEM_DYN>>>(
        Yhi, Ylo, NH, Whi + O_eW1, Wlo + O_eW1, NH, 8, Z,
        nullptr, 0, nullptr, nullptr, nullptr, nullptr, nullptr, nullptr, 0, nullptr);
    for (int t = 0; t < NT; t++) {
        k_gemm3<true><<<gStep, blk, SMEM_DYN>>>(
            hBhi[t & 1], hBlo[t & 1], NH, Whi + O_eU1, Wlo + O_eU1, NH, 8, nullptr,
            Z + (size_t)t * NG, (long long)NT * NG, Bias + 1 * NG, cB,
            hBhi[(t + 1) & 1], hBlo[(t + 1) & 1],
            nullptr, nullptr, 0, nullptr);
    }
    // --- decoder L0: zero input; continues from enc-L0 final state ---
    for (int t = 0; t < NSEG; t++) {
        k_gemm3<true><<<gStep, blk, SMEM_DYN>>>(
            hAhi[t & 1], hAlo[t & 1], NH, Whi + O_dU0, Wlo + O_dU0, NH, 8, nullptr,
            nullptr, 0, Bias + 2 * NG, cA,
            hAhi[(t + 1) & 1], hAlo[(t + 1) & 1],
            Yhi + (size_t)t * NH, Ylo + (size_t)t * NH, (long long)NSEG * NH, nullptr);
    }
    // --- decoder L1: precompute d0@dW1, then 32 steps, emit fp32 d1 ---
    k_gemm3<false><<<dim3(NB * NSEG / 64, 8), blk, SMEM_DYN>>>(
        Yhi, Ylo, NH, Whi + O_dW1, Wlo + O_dW1, NH, 8, Z,
        nullptr, 0, nullptr, nullptr, nullptr, nullptr, nullptr, nullptr, 0, nullptr);
    for (int t = 0; t < NSEG; t++) {
        k_gemm3<true><<<gStep, blk, SMEM_DYN>>>(
            hBhi[t & 1], hBlo[t & 1], NH, Whi + O_dU1, Wlo + O_dU1, NH, 8, nullptr,
            Z + (size_t)t * NG, (long long)NSEG * NG, Bias + 3 * NG, cB,
            hBhi[(t + 1) & 1], hBlo[(t + 1) & 1],
            nullptr, nullptr, (long long)NSEG * NH, D1 + (size_t)t * NH);
    }
    // --- final dense ---
    k_dense<<<NB * NSEG / 8, 256>>>(denseW, denseb, (float*)d_out);
}

// round 4
// speedup vs baseline: 1.4277x; 1.1764x over previous
#include <cuda_runtime.h>
#include <cuda_fp16.h>
#include <cstdint>
#include <cstddef>

#define NB 1024
#define NT 64
#define NF 121
#define NH 512
#define NSEG 32
#define NG 2048   // 4*H

// ---------------- scratch (device globals; no allocation) ----------------
__device__ __align__(16) float   g_Z   [(size_t)NB * NT * NG];    // precomputed z (interleaved cols)
__device__ __align__(16) __half  g_X   [(size_t)NB * NT * 128];   // x fp16, K padded 121->128
__device__ __align__(16) __half  g_Y   [(size_t)NB * NT * NH];    // y0 / d0 staging (fp16)
__device__ __align__(16) float   g_D1  [(size_t)NB * NSEG * NH];  // decoder L1 outputs
__device__ __align__(16) __half  g_hA  [2][NB * NH];              // ping-pong h (enc0->dec0)
__device__ __align__(16) __half  g_hB  [2][NB * NH];              // (enc1->dec1)
__device__ __align__(16) float   g_cA  [NB * NH];
__device__ __align__(16) float   g_cB  [NB * NH];
// weight arena: W^T, rows = interleaved out-col (j*4+gate), K contiguous. fp16 hi/lo.
#define O_eW0 0
#define O_eU0 (2048*128)
#define O_eW1 (O_eU0 + 2048*512)
#define O_eU1 (O_eW1 + 2048*512)
#define O_dU0 (O_eU1 + 2048*512)
#define O_dW1 (O_dU0 + 2048*512)
#define O_dU1 (O_dW1 + 2048*512)
#define W_TOTAL (O_dU1 + 2048*512)
__device__ __align__(16) __half  g_WhiT[W_TOTAL];
__device__ __align__(16) __half  g_WloT[W_TOTAL];
__device__ __align__(16) float   g_bias[4 * NG];   // eb0,eb1,db0,db1 (interleaved)

// ---------------- helpers ----------------
__device__ __forceinline__ void split2h(float v, __half& hi, __half& lo) {
    hi = __float2half(v);
    lo = __float2half(v - __half2float(hi));
}
__device__ __forceinline__ float sigf(float x) { return 1.0f / (1.0f + __expf(-x)); }

__device__ __forceinline__ uint32_t smem_u32(const void* p) {
    uint32_t a;
    asm("{ .reg .u64 t; cvta.to.shared.u64 t, %1; cvt.u32.u64 %0, t; }" : "=r"(a) : "l"(p));
    return a;
}
__device__ __forceinline__ void mma16816h(float* d, const unsigned* a, unsigned b0, unsigned b1) {
    asm volatile(
        "mma.sync.aligned.m16n8k16.row.col.f32.f16.f16.f32 "
        "{%0,%1,%2,%3}, {%4,%5,%6,%7}, {%8,%9}, {%0,%1,%2,%3};"
        : "+f"(d[0]), "+f"(d[1]), "+f"(d[2]), "+f"(d[3])
        : "r"(a[0]), "r"(a[1]), "r"(a[2]), "r"(a[3]), "r"(b0), "r"(b1));
}
__device__ __forceinline__ void ldsm4(uint32_t* r, uint32_t addr) {
    asm volatile("ldmatrix.sync.aligned.m8n8.x4.shared.b16 {%0,%1,%2,%3}, [%4];"
                 : "=r"(r[0]), "=r"(r[1]), "=r"(r[2]), "=r"(r[3]) : "r"(addr));
}
__device__ __forceinline__ void cpa16(uint32_t dst, const void* src) {
    asm volatile("cp.async.cg.shared.global [%0], [%1], 16;" :: "r"(dst), "l"(src));
}
#define CP_COMMIT() asm volatile("cp.async.commit_group;" ::: "memory")

// smem: two 72KB buffers: A 8K | Bhi 32K | Blo 32K
#define BUF_STRIDE 73728u
#define SMEM_DYN   (2 * 73728)

// ---------------- prep kernels ----------------
// W^T split: src [K][2048] -> dst [cil][Kpad], cil=(n%512)*4 + n/512, K contiguous
__global__ void k_split_weightT(const float* __restrict__ src, int K, int Kpad,
                                __half* __restrict__ dhi, __half* __restrict__ dlo) {
    int idx = blockIdx.x * blockDim.x + threadIdx.x;
    if (idx >= 2048 * Kpad) return;
    int n = idx / Kpad, k = idx % Kpad;
    float v = (k < K) ? src[(size_t)k * NG + n] : 0.0f;
    int cil = (n & 511) * 4 + (n >> 9);
    __half hi, lo; split2h(v, hi, lo);
    dhi[(size_t)cil * Kpad + k] = hi;
    dlo[(size_t)cil * Kpad + k] = lo;
}

__global__ void k_split_bias(const float* __restrict__ src, float* __restrict__ dst) {
    int n = blockIdx.x * blockDim.x + threadIdx.x;
    if (n >= NG) return;
    dst[(n & 511) * 4 + (n >> 9)] = src[n];
}

__global__ void k_split_x(const float* __restrict__ x) {
    int idx = blockIdx.x * blockDim.x + threadIdx.x;
    if (idx >= NB * NT * 128) return;
    int r = idx >> 7, k = idx & 127;
    float v = (k < NF) ? x[(size_t)r * NF + k] : 0.0f;
    g_X[idx] = __float2half(v);
}

__global__ void k_zero_states() {
    int idx = blockIdx.x * blockDim.x + threadIdx.x;
    if (idx >= NB * NH) return;
    __half z = __float2half(0.0f);
    g_hA[0][idx] = z; g_hB[0][idx] = z;
    g_cA[idx] = 0.0f; g_cB[idx] = 0.0f;
}

// ---------------- fp16x2 GEMM via mma.sync, cp.async double-buffered ----------------
// C[M][2048] = A[M][K] @ (Bhi+Blo)^T ; A fp16, B stored [n][k] K-contig fp16 hi/lo.
// Tile BM=64 x BN=256, 256 thr = 8 warps (2x4), warp tile 32x64. K chunks of 64.
template <bool LSTM>
__global__ __launch_bounds__(256)
void k_gemm3(const __half* __restrict__ A, int lda,
             const __half* __restrict__ Bhi, const __half* __restrict__ Blo, int ldw,
             int nc,
             float* __restrict__ outZ,
             const float* __restrict__ pre, long long preStride,
             const float* __restrict__ bias,
             float* __restrict__ cState,
             __half* __restrict__ hOut,
             __half* __restrict__ yOut, long long yStride,
             float* __restrict__ yF32) {
    extern __shared__ __align__(128) char smem[];
    const uint32_t sb = smem_u32(smem);
    const int tid = threadIdx.x, lane = tid & 31, warp = tid >> 5;
    const int wm = warp >> 2, wn = warp & 3;
    const int bm = blockIdx.x * 64;
    const int bn = blockIdx.y * 256;

    float acc[2][8][4];
#pragma unroll
    for (int a = 0; a < 2; a++)
#pragma unroll
        for (int b = 0; b < 8; b++)
#pragma unroll
            for (int c = 0; c < 4; c++) acc[a][b][c] = 0.0f;

    const uint32_t a_lc = (uint32_t)(lane & 16);            // ldmatrix col sel
    const uint32_t b_lc = (uint32_t)((lane & 8) << 1);
    const int b_r8 = (lane & 16) >> 1;

    auto issue = [&](int c) {
        const int kb = c * 64;
        const uint32_t dbase = sb + (uint32_t)(c & 1) * BUF_STRIDE;
        {   // A: 64 rows x 128B
#pragma unroll
            for (int it = 0; it < 2; it++) {
                int u = it * 256 + tid;
                int row = u >> 3, seg = u & 7;
                uint32_t off = (uint32_t)(row * 128) + (uint32_t)((seg * 16) ^ ((row & 7) * 16));
                cpa16(dbase + off, A + (size_t)(bm + row) * lda + kb + seg * 8);
            }
        }
#pragma unroll
        for (int m = 0; m < 2; m++) {                       // B hi/lo: 256 rows x 128B
            const __half* src = m ? Blo : Bhi;
            const uint32_t db = dbase + 8192u + (uint32_t)m * 32768u;
#pragma unroll
            for (int it = 0; it < 8; it++) {
                int u = it * 256 + tid;
                int row = u >> 3, seg = u & 7;
                uint32_t off = (uint32_t)(row * 128) + (uint32_t)((seg * 16) ^ ((row & 7) * 16));
                cpa16(db + off, src + (size_t)(bn + row) * ldw + kb + seg * 8);
            }
        }
        CP_COMMIT();
    };

    issue(0);
    for (int c = 0; c < nc; ++c) {
        if (c + 1 < nc) {
            issue(c + 1);
            asm volatile("cp.async.wait_group 1;" ::: "memory");
        } else {
            asm volatile("cp.async.wait_group 0;" ::: "memory");
        }
        __syncthreads();
        const uint32_t dbase = sb + (uint32_t)(c & 1) * BUF_STRIDE;
#pragma unroll
        for (int k16 = 0; k16 < 4; ++k16) {
            const uint32_t kcol = (uint32_t)(k16 * 32);
            uint32_t af[2][4];
#pragma unroll
            for (int mt = 0; mt < 2; ++mt) {
                int r = wm * 32 + mt * 16 + (lane & 15);
                uint32_t addr = dbase + (uint32_t)(r * 128)
                              + ((kcol + a_lc) ^ (uint32_t)((r & 7) * 16));
                ldsm4(af[mt], addr);
            }
            uint32_t bfr[2][8][2];
#pragma unroll
            for (int hl = 0; hl < 2; ++hl)
#pragma unroll
                for (int jq = 0; jq < 4; ++jq) {
                    int r = wn * 64 + jq * 16 + (lane & 7) + b_r8;
                    uint32_t addr = dbase + 8192u + (uint32_t)hl * 32768u + (uint32_t)(r * 128)
                                  + ((kcol + b_lc) ^ (uint32_t)((r & 7) * 16));
                    uint32_t t4[4];
                    ldsm4(t4, addr);
                    bfr[hl][jq * 2][0] = t4[0];     bfr[hl][jq * 2][1] = t4[1];
                    bfr[hl][jq * 2 + 1][0] = t4[2]; bfr[hl][jq * 2 + 1][1] = t4[3];
                }
#pragma unroll
            for (int jt = 0; jt < 8; ++jt)
#pragma unroll
                for (int mt = 0; mt < 2; ++mt) {
                    mma16816h(acc[mt][jt], af[mt], bfr[0][jt][0], bfr[0][jt][1]);  // A*Bhi
                    mma16816h(acc[mt][jt], af[mt], bfr[1][jt][0], bfr[1][jt][1]);  // A*Blo
                }
        }
        __syncthreads();
    }

    // ---------------- epilogue ----------------
    if (!LSTM) {
#pragma unroll
        for (int mt = 0; mt < 2; mt++) {
            int r = bm + wm * 32 + mt * 16 + (lane >> 2);
#pragma unroll
            for (int jt = 0; jt < 8; jt++) {
                int cix = bn + wn * 64 + jt * 8 + (lane & 3) * 2;
                float* o = outZ + (size_t)r * NG + cix;
                o[0] = acc[mt][jt][0]; o[1] = acc[mt][jt][1];
                o += (size_t)8 * NG;
                o[0] = acc[mt][jt][2]; o[1] = acc[mt][jt][3];
            }
        }
    } else {
#pragma unroll
        for (int mt = 0; mt < 2; mt++) {
            int rA = bm + wm * 32 + mt * 16 + (lane >> 2);
            int rB = rA + 8;
#pragma unroll
            for (int jt = 0; jt < 8; jt++) {
                int cix = bn + wn * 64 + jt * 8 + (lane & 3) * 2;
                float z0 = acc[mt][jt][0] + bias[cix];
                float z1 = acc[mt][jt][1] + bias[cix + 1];
                float z2 = acc[mt][jt][2] + bias[cix];
                float z3 = acc[mt][jt][3] + bias[cix + 1];
                if (pre) {
                    z0 += pre[(size_t)rA * preStride + cix];
                    z1 += pre[(size_t)rA * preStride + cix + 1];
                    z2 += pre[(size_t)rB * preStride + cix];
                    z3 += pre[(size_t)rB * preStride + cix + 1];
                }
                float p0 = __shfl_xor_sync(0xffffffffu, z0, 1);
                float p1 = __shfl_xor_sync(0xffffffffu, z1, 1);
                float p2 = __shfl_xor_sync(0xffffffffu, z2, 1);
                float p3 = __shfl_xor_sync(0xffffffffu, z3, 1);
                if (!(lane & 1)) {   // even lanes hold (i,f), received (g,o)
                    int j = cix >> 2;
#pragma unroll
                    for (int rr = 0; rr < 2; rr++) {
                        int r = rr ? rB : rA;
                        float zi = rr ? z2 : z0, zf = rr ? z3 : z1;
                        float zg = rr ? p2 : p0, zo = rr ? p3 : p1;
                        float ig = sigf(zi), fg = sigf(zf);
                        float gg = tanhf(zg), og = sigf(zo);
                        size_t si = (size_t)r * NH + j;
                        float cn = fg * cState[si] + ig * gg;
                        float h = og * tanhf(cn);
                        cState[si] = cn;
                        __half hh = __float2half(h);
                        hOut[si] = hh;
                        if (yOut) yOut[(size_t)r * yStride + j] = hh;
                        if (yF32) yF32[(size_t)r * yStride + j] = h;
                    }
                }
            }
        }
    }
}

// ---------------- final dense ----------------
__global__ void k_dense(const float* __restrict__ w, const float* __restrict__ b,
                        float* __restrict__ out) {
    int r = blockIdx.x * 8 + (threadIdx.x >> 5);
    int lane = threadIdx.x & 31;
    const float* row = g_D1 + (size_t)r * NH;
    float s = 0.0f;
#pragma unroll
    for (int k = lane; k < NH; k += 32) s += row[k] * w[k];
#pragma unroll
    for (int o = 16; o; o >>= 1) s += __shfl_xor_sync(0xffffffffu, s, o);
    if (lane == 0) out[r] = s + b[0];
}

// ---------------- host ----------------
extern "C" void kernel_launch(void* const* d_in, const int* in_sizes, int n_in,
                              void* d_out, int out_size) {
    (void)in_sizes; (void)n_in; (void)out_size;
    const float* x      = (const float*)d_in[0];
    const float* eW0    = (const float*)d_in[2];
    const float* eU0    = (const float*)d_in[3];
    const float* eb0    = (const float*)d_in[4];
    const float* eW1    = (const float*)d_in[5];
    const float* eU1    = (const float*)d_in[6];
    const float* eb1    = (const float*)d_in[7];
    const float* dU0    = (const float*)d_in[9];
    const float* db0    = (const float*)d_in[10];
    const float* dW1    = (const float*)d_in[11];
    const float* dU1    = (const float*)d_in[12];
    const float* db1    = (const float*)d_in[13];
    const float* denseW = (const float*)d_in[14];
    const float* denseb = (const float*)d_in[15];

    cudaFuncSetAttribute(k_gemm3<true>,  cudaFuncAttributeMaxDynamicSharedMemorySize, SMEM_DYN);
    cudaFuncSetAttribute(k_gemm3<false>, cudaFuncAttributeMaxDynamicSharedMemorySize, SMEM_DYN);

    void *pZ, *pX, *pY, *pD1, *pA, *pB, *pCA, *pCB, *pWh, *pWl, *pBs;
    cudaGetSymbolAddress(&pZ, g_Z);
    cudaGetSymbolAddress(&pX, g_X);
    cudaGetSymbolAddress(&pY, g_Y);
    cudaGetSymbolAddress(&pD1, g_D1);
    cudaGetSymbolAddress(&pA, g_hA);
    cudaGetSymbolAddress(&pB, g_hB);
    cudaGetSymbolAddress(&pCA, g_cA);  cudaGetSymbolAddress(&pCB, g_cB);
    cudaGetSymbolAddress(&pWh, g_WhiT); cudaGetSymbolAddress(&pWl, g_WloT);
    cudaGetSymbolAddress(&pBs, g_bias);

    float* Z = (float*)pZ;
    __half* X = (__half*)pX;
    __half* Y = (__half*)pY;
    float* D1 = (float*)pD1;
    __half* hA[2] = {(__half*)pA, (__half*)pA + NB * NH};
    __half* hB[2] = {(__half*)pB, (__half*)pB + NB * NH};
    float* cA = (float*)pCA; float* cB = (float*)pCB;
    __half* Whi = (__half*)pWh; __half* Wlo = (__half*)pWl;
    float* Bias = (float*)pBs;

    // --- prep ---
    auto sw = [&](const float* src, int K, int Kpad, size_t off) {
        int n = 2048 * Kpad;
        k_split_weightT<<<(n + 255) / 256, 256>>>(src, K, Kpad, Whi + off, Wlo + off);
    };
    sw(eW0, NF, 128, O_eW0);
    sw(eU0, NH, NH, O_eU0);
    sw(eW1, NH, NH, O_eW1);
    sw(eU1, NH, NH, O_eU1);
    sw(dU0, NH, NH, O_dU0);
    sw(dW1, NH, NH, O_dW1);
    sw(dU1, NH, NH, O_dU1);
    k_split_bias<<<8, 256>>>(eb0, Bias + 0 * NG);
    k_split_bias<<<8, 256>>>(eb1, Bias + 1 * NG);
    k_split_bias<<<8, 256>>>(db0, Bias + 2 * NG);
    k_split_bias<<<8, 256>>>(db1, Bias + 3 * NG);
    k_split_x<<<(NB * NT * 128) / 256, 256>>>(x);
    k_zero_states<<<(NB * NH) / 256, 256>>>();

    const dim3 blk(256);
    const dim3 gStep(NB / 64, 8);   // 128 CTAs

    // --- encoder L0: precompute x@eW0, then 64 recurrent steps ---
    k_gemm3<false><<<dim3(NB * NT / 64, 8), blk, SMEM_DYN>>>(
        X, 128, Whi + O_eW0, Wlo + O_eW0, 128, 2, Z,
        nullptr, 0, nullptr, nullptr, nullptr, nullptr, 0, nullptr);
    for (int t = 0; t < NT; t++) {
        k_gemm3<true><<<gStep, blk, SMEM_DYN>>>(
            hA[t & 1], NH, Whi + O_eU0, Wlo + O_eU0, NH, 8, nullptr,
            Z + (size_t)t * NG, (long long)NT * NG, Bias + 0 * NG, cA,
            hA[(t + 1) & 1],
            Y + (size_t)t * NH, (long long)NT * NH, nullptr);
    }
    // --- encoder L1: precompute y0@eW1, then 64 steps ---
    k_gemm3<false><<<dim3(NB * NT / 64, 8), blk, SMEM_DYN>>>(
        Y, NH, Whi + O_eW1, Wlo + O_eW1, NH, 8, Z,
        nullptr, 0, nullptr, nullptr, nullptr, nullptr, 0, nullptr);
    for (int t = 0; t < NT; t++) {
        k_gemm3<true><<<gStep, blk, SMEM_DYN>>>(
            hB[t & 1], NH, Whi + O_eU1, Wlo + O_eU1, NH, 8, nullptr,
            Z + (size_t)t * NG, (long long)NT * NG, Bias + 1 * NG, cB,
            hB[(t + 1) & 1],
            nullptr, 0, nullptr);
    }
    // --- decoder L0: zero input; continues from enc-L0 final state ---
    for (int t = 0; t < NSEG; t++) {
        k_gemm3<true><<<gStep, blk, SMEM_DYN>>>(
            hA[t & 1], NH, Whi + O_dU0, Wlo + O_dU0, NH, 8, nullptr,
            nullptr, 0, Bias + 2 * NG, cA,
            hA[(t + 1) & 1],
            Y + (size_t)t * NH, (long long)NSEG * NH, nullptr);
    }
    // --- decoder L1: precompute d0@dW1, then 32 steps, emit fp32 d1 ---
    k_gemm3<false><<<dim3(NB * NSEG / 64, 8), blk, SMEM_DYN>>>(
        Y, NH, Whi + O_dW1, Wlo + O_dW1, NH, 8, Z,
        nullptr, 0, nullptr, nullptr, nullptr, nullptr, 0, nullptr);
    for (int t = 0; t < NSEG; t++) {
        k_gemm3<true><<<gStep, blk, SMEM_DYN>>>(
            hB[t & 1], NH, Whi + O_dU1, Wlo + O_dU1, NH, 8, nullptr,
            Z + (size_t)t * NG, (long long)NSEG * NG, Bias + 3 * NG, cB,
            hB[(t + 1) & 1],
            nullptr, (long long)NSEG * NH, D1 + (size_t)t * NH);
    }
    // --- final dense ---
    k_dense<<<NB * NSEG / 8, 256>>>(denseW, denseb, (float*)d_out);
}

// round 6
// speedup vs baseline: 1.4383x; 1.0074x over previous
#include <cuda_runtime.h>
#include <cuda_fp16.h>
#include <cstdint>
#include <cstddef>

#define NB 1024
#define NT 64
#define NF 121
#define NH 512
#define NSEG 32
#define NG 2048   // 4*H

// ---------------- scratch (device globals; no allocation) ----------------
__device__ __align__(16) float   g_Z   [(size_t)NB * NT * NG];    // precomputed z (interleaved cols)
__device__ __align__(16) __half  g_X   [(size_t)NB * NT * 128];   // x fp16, K padded 121->128
__device__ __align__(16) __half  g_Y   [(size_t)NB * NT * NH];    // y0 / d0 staging (fp16)
__device__ __align__(16) float   g_D1  [(size_t)NB * NSEG * NH];  // decoder L1 outputs
__device__ __align__(16) __half  g_hA  [2][NB * NH];              // ping-pong h (enc0->dec0)
__device__ __align__(16) __half  g_hB  [2][NB * NH];              // (enc1->dec1)
__device__ __align__(16) float   g_cA  [NB * NH];
__device__ __align__(16) float   g_cB  [NB * NH];
// weight arena: W^T, rows = interleaved out-col (j*4+gate), K contiguous. fp16 hi/lo.
#define O_eW0 0
#define O_eU0 (2048*128)
#define O_eW1 (O_eU0 + 2048*512)
#define O_eU1 (O_eW1 + 2048*512)
#define O_dU0 (O_eU1 + 2048*512)
#define O_dW1 (O_dU0 + 2048*512)
#define O_dU1 (O_dW1 + 2048*512)
#define W_TOTAL (O_dU1 + 2048*512)
__device__ __align__(16) __half  g_WhiT[W_TOTAL];
__device__ __align__(16) __half  g_WloT[W_TOTAL];
__device__ __align__(16) float   g_bias[4 * NG];   // eb0,eb1,db0,db1 (interleaved)

// ---------------- helpers ----------------
__device__ __forceinline__ void split2h(float v, __half& hi, __half& lo) {
    hi = __float2half(v);
    lo = __float2half(v - __half2float(hi));
}
__device__ __forceinline__ float rcpa(float x) {
    float r; asm("rcp.approx.f32 %0, %1;" : "=f"(r) : "f"(x)); return r;
}
// sigmoid / tanh via MUFU ex2 + rcp.approx (rel err ~2^-22, fast)
__device__ __forceinline__ float sigf(float x)  { return rcpa(1.0f + __expf(-x)); }
__device__ __forceinline__ float tanhff(float x){ return __fmaf_rn(2.0f, rcpa(1.0f + __expf(-2.0f * x)), -1.0f); }

__device__ __forceinline__ uint32_t smem_u32(const void* p) {
    uint32_t a;
    asm("{ .reg .u64 t; cvta.to.shared.u64 t, %1; cvt.u32.u64 %0, t; }" : "=r"(a) : "l"(p));
    return a;
}
__device__ __forceinline__ void mma16816h(float* d, const unsigned* a, unsigned b0, unsigned b1) {
    asm volatile(
        "mma.sync.aligned.m16n8k16.row.col.f32.f16.f16.f32 "
        "{%0,%1,%2,%3}, {%4,%5,%6,%7}, {%8,%9}, {%0,%1,%2,%3};"
        : "+f"(d[0]), "+f"(d[1]), "+f"(d[2]), "+f"(d[3])
        : "r"(a[0]), "r"(a[1]), "r"(a[2]), "r"(a[3]), "r"(b0), "r"(b1));
}
__device__ __forceinline__ void ldsm4(uint32_t* r, uint32_t addr) {
    asm volatile("ldmatrix.sync.aligned.m8n8.x4.shared.b16 {%0,%1,%2,%3}, [%4];"
                 : "=r"(r[0]), "=r"(r[1]), "=r"(r[2]), "=r"(r[3]) : "r"(addr));
}
__device__ __forceinline__ void cpa16(uint32_t dst, const void* src) {
    asm volatile("cp.async.cg.shared.global [%0], [%1], 16;" :: "r"(dst), "l"(src));
}
#define CP_COMMIT() asm volatile("cp.async.commit_group;" ::: "memory")

// smem: two 72KB buffers: A 8K | Bhi 32K | Blo 32K
#define BUF_STRIDE 73728u
#define SMEM_DYN   (2 * 73728)

// ---------------- prep kernels ----------------
__global__ void k_split_weightT(const float* __restrict__ src, int K, int Kpad,
                                __half* __restrict__ dhi, __half* __restrict__ dlo) {
    int idx = blockIdx.x * blockDim.x + threadIdx.x;
    if (idx >= 2048 * Kpad) return;
    int n = idx / Kpad, k = idx % Kpad;
    float v = (k < K) ? src[(size_t)k * NG + n] : 0.0f;
    int cil = (n & 511) * 4 + (n >> 9);
    __half hi, lo; split2h(v, hi, lo);
    dhi[(size_t)cil * Kpad + k] = hi;
    dlo[(size_t)cil * Kpad + k] = lo;
}

__global__ void k_split_bias(const float* __restrict__ src, float* __restrict__ dst) {
    int n = blockIdx.x * blockDim.x + threadIdx.x;
    if (n >= NG) return;
    dst[(n & 511) * 4 + (n >> 9)] = src[n];
}

__global__ void k_split_x(const float* __restrict__ x) {
    int idx = blockIdx.x * blockDim.x + threadIdx.x;
    if (idx >= NB * NT * 128) return;
    int r = idx >> 7, k = idx & 127;
    float v = (k < NF) ? x[(size_t)r * NF + k] : 0.0f;
    g_X[idx] = __float2half(v);
}

__global__ void k_zero_states() {
    int idx = blockIdx.x * blockDim.x + threadIdx.x;
    if (idx >= NB * NH) return;
    __half z = __float2half(0.0f);
    g_hA[0][idx] = z; g_hB[0][idx] = z;
    g_cA[idx] = 0.0f; g_cB[idx] = 0.0f;
}

// ---------------- fp16x2 GEMM via mma.sync, cp.async double-buffered ----------------
// C[M][2048] = A[M][K] @ (Bhi+Blo)^T ; A fp16, B stored [n][k] K-contig fp16 hi/lo.
// Tile BM=64 x BN=256, 256 thr = 8 warps (2x4), warp tile 32x64. K chunks of 64.
template <bool LSTM>
__global__ __launch_bounds__(256)
void k_gemm3(const __half* __restrict__ A, int lda,
             const __half* __restrict__ Bhi, const __half* __restrict__ Blo, int ldw,
             int nc,
             float* __restrict__ outZ,
             const float* __restrict__ pre, long long preStride,
             const float* __restrict__ bias,
             float* __restrict__ cState,
             __half* __restrict__ hOut,
             __half* __restrict__ yOut, long long yStride,
             float* __restrict__ yF32) {
    extern __shared__ __align__(128) char smem[];
    const uint32_t sb = smem_u32(smem);
    const int tid = threadIdx.x, lane = tid & 31, warp = tid >> 5;
    const int wm = warp >> 2, wn = warp & 3;
    const int bm = blockIdx.x * 64;
    const int bn = blockIdx.y * 256;

    float acc[2][8][4];
#pragma unroll
    for (int a = 0; a < 2; a++)
#pragma unroll
        for (int b = 0; b < 8; b++)
#pragma unroll
            for (int c = 0; c < 4; c++) acc[a][b][c] = 0.0f;

    const uint32_t a_lc = (uint32_t)(lane & 16);            // ldmatrix col sel
    const uint32_t b_lc = (uint32_t)((lane & 8) << 1);
    const int b_r8 = (lane & 16) >> 1;

    auto issue = [&](int c) {
        const int kb = c * 64;
        const uint32_t dbase = sb + (uint32_t)(c & 1) * BUF_STRIDE;
        {   // A: 64 rows x 128B
#pragma unroll
            for (int it = 0; it < 2; it++) {
                int u = it * 256 + tid;
                int row = u >> 3, seg = u & 7;
                uint32_t off = (uint32_t)(row * 128) + (uint32_t)((seg * 16) ^ ((row & 7) * 16));
                cpa16(dbase + off, A + (size_t)(bm + row) * lda + kb + seg * 8);
            }
        }
#pragma unroll
        for (int m = 0; m < 2; m++) {                       // B hi/lo: 256 rows x 128B
            const __half* src = m ? Blo : Bhi;
            const uint32_t db = dbase + 8192u + (uint32_t)m * 32768u;
#pragma unroll
            for (int it = 0; it < 8; it++) {
                int u = it * 256 + tid;
                int row = u >> 3, seg = u & 7;
                uint32_t off = (uint32_t)(row * 128) + (uint32_t)((seg * 16) ^ ((row & 7) * 16));
                cpa16(db + off, src + (size_t)(bn + row) * ldw + kb + seg * 8);
            }
        }
        CP_COMMIT();
    };

    issue(0);
    for (int c = 0; c < nc; ++c) {
        if (c + 1 < nc) {
            issue(c + 1);
            asm volatile("cp.async.wait_group 1;" ::: "memory");
        } else {
            asm volatile("cp.async.wait_group 0;" ::: "memory");
        }
        __syncthreads();
        const uint32_t dbase = sb + (uint32_t)(c & 1) * BUF_STRIDE;
#pragma unroll
        for (int k16 = 0; k16 < 4; ++k16) {
            const uint32_t kcol = (uint32_t)(k16 * 32);
            uint32_t af[2][4];
#pragma unroll
            for (int mt = 0; mt < 2; ++mt) {
                int r = wm * 32 + mt * 16 + (lane & 15);
                uint32_t addr = dbase + (uint32_t)(r * 128)
                              + ((kcol + a_lc) ^ (uint32_t)((r & 7) * 16));
                ldsm4(af[mt], addr);
            }
            uint32_t bfr[2][8][2];
#pragma unroll
            for (int hl = 0; hl < 2; ++hl)
#pragma unroll
                for (int jq = 0; jq < 4; ++jq) {
                    int r = wn * 64 + jq * 16 + (lane & 7) + b_r8;
                    uint32_t addr = dbase + 8192u + (uint32_t)hl * 32768u + (uint32_t)(r * 128)
                                  + ((kcol + b_lc) ^ (uint32_t)((r & 7) * 16));
                    uint32_t t4[4];
                    ldsm4(t4, addr);
                    bfr[hl][jq * 2][0] = t4[0];     bfr[hl][jq * 2][1] = t4[1];
                    bfr[hl][jq * 2 + 1][0] = t4[2]; bfr[hl][jq * 2 + 1][1] = t4[3];
                }
#pragma unroll
            for (int jt = 0; jt < 8; ++jt)
#pragma unroll
                for (int mt = 0; mt < 2; ++mt) {
                    mma16816h(acc[mt][jt], af[mt], bfr[0][jt][0], bfr[0][jt][1]);  // A*Bhi
                    mma16816h(acc[mt][jt], af[mt], bfr[1][jt][0], bfr[1][jt][1]);  // A*Blo
                }
        }
        __syncthreads();
    }

    // ---------------- epilogue ----------------
    if (!LSTM) {
#pragma unroll
        for (int mt = 0; mt < 2; mt++) {
            int r = bm + wm * 32 + mt * 16 + (lane >> 2);
#pragma unroll
            for (int jt = 0; jt < 8; jt++) {
                int cix = bn + wn * 64 + jt * 8 + (lane & 3) * 2;
                float* o = outZ + (size_t)r * NG + cix;
                o[0] = acc[mt][jt][0]; o[1] = acc[mt][jt][1];
                o += (size_t)8 * NG;
                o[0] = acc[mt][jt][2]; o[1] = acc[mt][jt][3];
            }
        }
    } else {
        // all-lane LSTM epilogue: even lane -> row rA, odd lane -> row rB=rA+8.
        // Gate interleave: col cix carries gate (cix&3); even lanes hold (i,f),
        // odd lanes hold (g,o) of the same j. Exchange halves so every lane
        // assembles one complete (i,f,g,o) quadruple.
        const int par = lane & 1;
#pragma unroll
        for (int mt = 0; mt < 2; mt++) {
            const int rA = bm + wm * 32 + mt * 16 + (lane >> 2);
            const int r  = rA + par * 8;
#pragma unroll
            for (int jt = 0; jt < 8; jt++) {
                const int cix = bn + wn * 64 + jt * 8 + (lane & 3) * 2;
                float z0 = acc[mt][jt][0] + bias[cix];
                float z1 = acc[mt][jt][1] + bias[cix + 1];
                float z2 = acc[mt][jt][2] + bias[cix];
                float z3 = acc[mt][jt][3] + bias[cix + 1];
                if (pre) {
                    z0 += pre[(size_t)rA * preStride + cix];
                    z1 += pre[(size_t)rA * preStride + cix + 1];
                    z2 += pre[(size_t)(rA + 8) * preStride + cix];
                    z3 += pre[(size_t)(rA + 8) * preStride + cix + 1];
                }
                // odd lane sends its rA pair (g,o); even lane sends its rB pair (i,f)
                float s0 = par ? z0 : z2;
                float s1 = par ? z1 : z3;
                float q0 = __shfl_xor_sync(0xffffffffu, s0, 1);
                float q1 = __shfl_xor_sync(0xffffffffu, s1, 1);
                float zi = par ? q0 : z0;
                float zf = par ? q1 : z1;
                float zg = par ? z2 : q0;
                float zo = par ? z3 : q1;
                const int j = cix >> 2;     // same j for both parities
                const size_t si = (size_t)r * NH + j;
                float ig = sigf(zi), fg = sigf(zf), og = sigf(zo);
                float gg = tanhff(zg);
                float cn = fg * cState[si] + ig * gg;
                float h = og * tanhff(cn);
                cState[si] = cn;
                __half hh = __float2half(h);
                hOut[si] = hh;
                if (yOut) yOut[(size_t)r * yStride + j] = hh;
                if (yF32) yF32[(size_t)r * yStride + j] = h;
            }
        }
    }
}

// ---------------- final dense ----------------
__global__ void k_dense(const float* __restrict__ w, const float* __restrict__ b,
                        float* __restrict__ out) {
    int r = blockIdx.x * 8 + (threadIdx.x >> 5);
    int lane = threadIdx.x & 31;
    const float* row = g_D1 + (size_t)r * NH;
    float s = 0.0f;
#pragma unroll
    for (int k = lane; k < NH; k += 32) s += row[k] * w[k];
#pragma unroll
    for (int o = 16; o; o >>= 1) s += __shfl_xor_sync(0xffffffffu, s, o);
    if (lane == 0) out[r] = s + b[0];
}

// ---------------- host ----------------
extern "C" void kernel_launch(void* const* d_in, const int* in_sizes, int n_in,
                              void* d_out, int out_size) {
    (void)in_sizes; (void)n_in; (void)out_size;
    const float* x      = (const float*)d_in[0];
    const float* eW0    = (const float*)d_in[2];
    const float* eU0    = (const float*)d_in[3];
    const float* eb0    = (const float*)d_in[4];
    const float* eW1    = (const float*)d_in[5];
    const float* eU1    = (const float*)d_in[6];
    const float* eb1    = (const float*)d_in[7];
    const float* dU0    = (const float*)d_in[9];
    const float* db0    = (const float*)d_in[10];
    const float* dW1    = (const float*)d_in[11];
    const float* dU1    = (const float*)d_in[12];
    const float* db1    = (const float*)d_in[13];
    const float* denseW = (const float*)d_in[14];
    const float* denseb = (const float*)d_in[15];

    cudaFuncSetAttribute(k_gemm3<true>,  cudaFuncAttributeMaxDynamicSharedMemorySize, SMEM_DYN);
    cudaFuncSetAttribute(k_gemm3<false>, cudaFuncAttributeMaxDynamicSharedMemorySize, SMEM_DYN);

    void *pZ, *pX, *pY, *pD1, *pA, *pB, *pCA, *pCB, *pWh, *pWl, *pBs;
    cudaGetSymbolAddress(&pZ, g_Z);
    cudaGetSymbolAddress(&pX, g_X);
    cudaGetSymbolAddress(&pY, g_Y);
    cudaGetSymbolAddress(&pD1, g_D1);
    cudaGetSymbolAddress(&pA, g_hA);
    cudaGetSymbolAddress(&pB, g_hB);
    cudaGetSymbolAddress(&pCA, g_cA);  cudaGetSymbolAddress(&pCB, g_cB);
    cudaGetSymbolAddress(&pWh, g_WhiT); cudaGetSymbolAddress(&pWl, g_WloT);
    cudaGetSymbolAddress(&pBs, g_bias);

    float* Z = (float*)pZ;
    __half* X = (__half*)pX;
    __half* Y = (__half*)pY;
    float* D1 = (float*)pD1;
    __half* hA[2] = {(__half*)pA, (__half*)pA + NB * NH};
    __half* hB[2] = {(__half*)pB, (__half*)pB + NB * NH};
    float* cA = (float*)pCA; float* cB = (float*)pCB;
    __half* Whi = (__half*)pWh; __half* Wlo = (__half*)pWl;
    float* Bias = (float*)pBs;

    // --- prep ---
    auto sw = [&](const float* src, int K, int Kpad, size_t off) {
        int n = 2048 * Kpad;
        k_split_weightT<<<(n + 255) / 256, 256>>>(src, K, Kpad, Whi + off, Wlo + off);
    };
    sw(eW0, NF, 128, O_eW0);
    sw(eU0, NH, NH, O_eU0);
    sw(eW1, NH, NH, O_eW1);
    sw(eU1, NH, NH, O_eU1);
    sw(dU0, NH, NH, O_dU0);
    sw(dW1, NH, NH, O_dW1);
    sw(dU1, NH, NH, O_dU1);
    k_split_bias<<<8, 256>>>(eb0, Bias + 0 * NG);
    k_split_bias<<<8, 256>>>(eb1, Bias + 1 * NG);
    k_split_bias<<<8, 256>>>(db0, Bias + 2 * NG);
    k_split_bias<<<8, 256>>>(db1, Bias + 3 * NG);
    k_split_x<<<(NB * NT * 128) / 256, 256>>>(x);
    k_zero_states<<<(NB * NH) / 256, 256>>>();

    const dim3 blk(256);
    const dim3 gStep(NB / 64, 8);   // 128 CTAs

    // --- encoder L0: precompute x@eW0, then 64 recurrent steps ---
    k_gemm3<false><<<dim3(NB * NT / 64, 8), blk, SMEM_DYN>>>(
        X, 128, Whi + O_eW0, Wlo + O_eW0, 128, 2, Z,
        nullptr, 0, nullptr, nullptr, nullptr, nullptr, 0, nullptr);
    for (int t = 0; t < NT; t++) {
        k_gemm3<true><<<gStep, blk, SMEM_DYN>>>(
            hA[t & 1], NH, Whi + O_eU0, Wlo + O_eU0, NH, 8, nullptr,
            Z + (size_t)t * NG, (long long)NT * NG, Bias + 0 * NG, cA,
            hA[(t + 1) & 1],
            Y + (size_t)t * NH, (long long)NT * NH, nullptr);
    }
    // --- encoder L1: precompute y0@eW1, then 64 steps ---
    k_gemm3<false><<<dim3(NB * NT / 64, 8), blk, SMEM_DYN>>>(
        Y, NH, Whi + O_eW1, Wlo + O_eW1, NH, 8, Z,
        nullptr, 0, nullptr, nullptr, nullptr, nullptr, 0, nullptr);
    for (int t = 0; t < NT; t++) {
        k_gemm3<true><<<gStep, blk, SMEM_DYN>>>(
            hB[t & 1], NH, Whi + O_eU1, Wlo + O_eU1, NH, 8, nullptr,
            Z + (size_t)t * NG, (long long)NT * NG, Bias + 1 * NG, cB,
            hB[(t + 1) & 1],
            nullptr, 0, nullptr);
    }
    // --- decoder L0: zero input; continues from enc-L0 final state ---
    for (int t = 0; t < NSEG; t++) {
        k_gemm3<true><<<gStep, blk, SMEM_DYN>>>(
            hA[t & 1], NH, Whi + O_dU0, Wlo + O_dU0, NH, 8, nullptr,
            nullptr, 0, Bias + 2 * NG, cA,
            hA[(t + 1) & 1],
            Y + (size_t)t * NH, (long long)NSEG * NH, nullptr);
    }
    // --- decoder L1: precompute d0@dW1, then 32 steps, emit fp32 d1 ---
    k_gemm3<false><<<dim3(NB * NSEG / 64, 8), blk, SMEM_DYN>>>(
        Y, NH, Whi + O_dW1, Wlo + O_dW1, NH, 8, Z,
        nullptr, 0, nullptr, nullptr, nullptr, nullptr, 0, nullptr);
    for (int t = 0; t < NSEG; t++) {
        k_gemm3<true><<<gStep, blk, SMEM_DYN>>>(
            hB[t & 1], NH, Whi + O_dU1, Wlo + O_dU1, NH, 8, nullptr,
            Z + (size_t)t * NG, (long long)NSEG * NG, Bias + 3 * NG, cB,
            hB[(t + 1) & 1],
            nullptr, (long long)NSEG * NH, D1 + (size_t)t * NH);
    }
    // --- final dense ---
    k_dense<<<NB * NSEG / 8, 256>>>(denseW, denseb, (float*)d_out);
}

// round 7
// speedup vs baseline: 1.7918x; 1.2458x over previous
#include <cuda_runtime.h>
#include <cuda_fp16.h>
#include <cstdint>
#include <cstddef>

#define NB 1024
#define NT 64
#define NF 121
#define NH 512
#define NSEG 32
#define NG 2048   // 4*H

// ---------------- scratch (device globals; no allocation) ----------------
__device__ __align__(16) float   g_Z   [(size_t)NB * NT * NG];    // precomputed z (interleaved cols)
__device__ __align__(16) __half  g_X   [(size_t)NB * NT * 128];   // x fp16, K padded 121->128
__device__ __align__(16) __half  g_Y   [(size_t)NB * NT * NH];    // y0 / d0 staging (fp16)
__device__ __align__(16) float   g_D1  [(size_t)NB * NSEG * NH];  // decoder L1 outputs
__device__ __align__(16) __half  g_hA  [2][NB * NH];              // ping-pong h (enc0->dec0)
__device__ __align__(16) __half  g_hB  [2][NB * NH];              // (enc1->dec1)
__device__ __align__(16) float   g_cA  [NB * NH];
__device__ __align__(16) float   g_cB  [NB * NH];
// weight arena: W^T fp16, rows = interleaved out-col (j*4+gate), K contiguous.
#define O_eW0 0
#define O_eU0 (2048*128)
#define O_eW1 (O_eU0 + 2048*512)
#define O_eU1 (O_eW1 + 2048*512)
#define O_dU0 (O_eU1 + 2048*512)
#define O_dW1 (O_dU0 + 2048*512)
#define O_dU1 (O_dW1 + 2048*512)
#define W_TOTAL (O_dU1 + 2048*512)
__device__ __align__(16) __half  g_WT  [W_TOTAL];
__device__ __align__(16) float   g_bias[4 * NG];   // eb0,eb1,db0,db1 (interleaved)

// ---------------- helpers ----------------
__device__ __forceinline__ float rcpa(float x) {
    float r; asm("rcp.approx.f32 %0, %1;" : "=f"(r) : "f"(x)); return r;
}
__device__ __forceinline__ float sigf(float x)  { return rcpa(1.0f + __expf(-x)); }
__device__ __forceinline__ float tanhff(float x){ return __fmaf_rn(2.0f, rcpa(1.0f + __expf(-2.0f * x)), -1.0f); }

__device__ __forceinline__ uint32_t smem_u32(const void* p) {
    uint32_t a;
    asm("{ .reg .u64 t; cvta.to.shared.u64 t, %1; cvt.u32.u64 %0, t; }" : "=r"(a) : "l"(p));
    return a;
}
__device__ __forceinline__ void mma16816h(float* d, const unsigned* a, unsigned b0, unsigned b1) {
    asm volatile(
        "mma.sync.aligned.m16n8k16.row.col.f32.f16.f16.f32 "
        "{%0,%1,%2,%3}, {%4,%5,%6,%7}, {%8,%9}, {%0,%1,%2,%3};"
        : "+f"(d[0]), "+f"(d[1]), "+f"(d[2]), "+f"(d[3])
        : "r"(a[0]), "r"(a[1]), "r"(a[2]), "r"(a[3]), "r"(b0), "r"(b1));
}
__device__ __forceinline__ void ldsm4(uint32_t* r, uint32_t addr) {
    asm volatile("ldmatrix.sync.aligned.m8n8.x4.shared.b16 {%0,%1,%2,%3}, [%4];"
                 : "=r"(r[0]), "=r"(r[1]), "=r"(r[2]), "=r"(r[3]) : "r"(addr));
}
__device__ __forceinline__ void cpa16(uint32_t dst, const void* src) {
    asm volatile("cp.async.cg.shared.global [%0], [%1], 16;" :: "r"(dst), "l"(src));
}
#define CP_COMMIT() asm volatile("cp.async.commit_group;" ::: "memory")

// smem: two 40KB buffers: A 8K | B 32K
#define BUF_STRIDE 40960u
#define SMEM_DYN   (2 * 40960)

// ---------------- merged prep kernels ----------------
// All 7 weight matrices -> fp16 W^T arena, one launch.
// flat idx over [matrix][n(2048)][kpad]; cil = (n%512)*4 + n/512, dst[O + cil*Kpad + k]
__global__ void k_prep_weights(const float* __restrict__ eW0, const float* __restrict__ eU0,
                               const float* __restrict__ eW1, const float* __restrict__ eU1,
                               const float* __restrict__ dU0, const float* __restrict__ dW1,
                               const float* __restrict__ dU1) {
    long long idx = (long long)blockIdx.x * blockDim.x + threadIdx.x;
    const float* src; int K, Kpad; size_t off;
    const long long S0 = 2048LL * 128, S = 2048LL * 512;
    if (idx < S0)               { src = eW0; K = NF;  Kpad = 128; off = O_eW0; }
    else if ((idx -= S0) < S)   { src = eU0; K = NH;  Kpad = 512; off = O_eU0; }
    else if ((idx -= S) < S)    { src = eW1; K = NH;  Kpad = 512; off = O_eW1; }
    else if ((idx -= S) < S)    { src = eU1; K = NH;  Kpad = 512; off = O_eU1; }
    else if ((idx -= S) < S)    { src = dU0; K = NH;  Kpad = 512; off = O_dU0; }
    else if ((idx -= S) < S)    { src = dW1; K = NH;  Kpad = 512; off = O_dW1; }
    else if ((idx -= S) < S)    { src = dU1; K = NH;  Kpad = 512; off = O_dU1; }
    else return;
    int n = (int)(idx / Kpad), k = (int)(idx % Kpad);
    float v = (k < K) ? src[(size_t)k * NG + n] : 0.0f;
    int cil = (n & 511) * 4 + (n >> 9);
    g_WT[off + (size_t)cil * Kpad + k] = __float2half(v);
}

// biases + x split + state zeroing, one launch.
__global__ void k_prep_misc(const float* __restrict__ x,
                            const float* __restrict__ eb0, const float* __restrict__ eb1,
                            const float* __restrict__ db0, const float* __restrict__ db1) {
    long long idx = (long long)blockIdx.x * blockDim.x + threadIdx.x;
    if (idx < 4 * NG) {
        int which = (int)(idx >> 11), n = (int)(idx & 2047);
        const float* b = (which == 0) ? eb0 : (which == 1) ? eb1 : (which == 2) ? db0 : db1;
        g_bias[which * NG + (n & 511) * 4 + (n >> 9)] = b[n];
        return;
    }
    idx -= 4 * NG;
    if (idx < (long long)NB * NT * 128) {
        int r = (int)(idx >> 7), k = (int)(idx & 127);
        g_X[idx] = __float2half((k < NF) ? x[(size_t)r * NF + k] : 0.0f);
        return;
    }
    idx -= (long long)NB * NT * 128;
    if (idx < NB * NH) {
        __half z = __float2half(0.0f);
        g_hA[0][idx] = z; g_hB[0][idx] = z;
        g_cA[idx] = 0.0f; g_cB[idx] = 0.0f;
    }
}

// ---------------- fp16 GEMM via mma.sync, cp.async double-buffered ----------------
// C[M][2048] = A[M][K] @ B^T ; A fp16, B stored [n][k] K-contig fp16.
// Tile BM=64 x BN=256, 256 thr = 8 warps (2x4), warp tile 32x64. K chunks of 64.
template <bool LSTM>
__global__ __launch_bounds__(256)
void k_gemm1(const __half* __restrict__ A, int lda,
             const __half* __restrict__ B, int ldw,
             int nc,
             float* __restrict__ outZ,
             const float* __restrict__ pre, long long preStride,
             const float* __restrict__ bias,
             float* __restrict__ cState,
             __half* __restrict__ hOut,
             __half* __restrict__ yOut, long long yStride,
             float* __restrict__ yF32) {
    extern __shared__ __align__(128) char smem[];
    const uint32_t sb = smem_u32(smem);
    const int tid = threadIdx.x, lane = tid & 31, warp = tid >> 5;
    const int wm = warp >> 2, wn = warp & 3;
    const int bm = blockIdx.x * 64;
    const int bn = blockIdx.y * 256;

    float acc[2][8][4];
#pragma unroll
    for (int a = 0; a < 2; a++)
#pragma unroll
        for (int b = 0; b < 8; b++)
#pragma unroll
            for (int c = 0; c < 4; c++) acc[a][b][c] = 0.0f;

    const uint32_t a_lc = (uint32_t)(lane & 16);            // ldmatrix col sel
    const uint32_t b_lc = (uint32_t)((lane & 8) << 1);
    const int b_r8 = (lane & 16) >> 1;

    auto issue = [&](int c) {
        const int kb = c * 64;
        const uint32_t dbase = sb + (uint32_t)(c & 1) * BUF_STRIDE;
        {   // A: 64 rows x 128B
#pragma unroll
            for (int it = 0; it < 2; it++) {
                int u = it * 256 + tid;
                int row = u >> 3, seg = u & 7;
                uint32_t off = (uint32_t)(row * 128) + (uint32_t)((seg * 16) ^ ((row & 7) * 16));
                cpa16(dbase + off, A + (size_t)(bm + row) * lda + kb + seg * 8);
            }
        }
        {   // B: 256 rows x 128B
            const uint32_t db = dbase + 8192u;
#pragma unroll
            for (int it = 0; it < 8; it++) {
                int u = it * 256 + tid;
                int row = u >> 3, seg = u & 7;
                uint32_t off = (uint32_t)(row * 128) + (uint32_t)((seg * 16) ^ ((row & 7) * 16));
                cpa16(db + off, B + (size_t)(bn + row) * ldw + kb + seg * 8);
            }
        }
        CP_COMMIT();
    };

    issue(0);
    for (int c = 0; c < nc; ++c) {
        if (c + 1 < nc) {
            issue(c + 1);
            asm volatile("cp.async.wait_group 1;" ::: "memory");
        } else {
            asm volatile("cp.async.wait_group 0;" ::: "memory");
        }
        __syncthreads();
        const uint32_t dbase = sb + (uint32_t)(c & 1) * BUF_STRIDE;
#pragma unroll
        for (int k16 = 0; k16 < 4; ++k16) {
            const uint32_t kcol = (uint32_t)(k16 * 32);
            uint32_t af[2][4];
#pragma unroll
            for (int mt = 0; mt < 2; ++mt) {
                int r = wm * 32 + mt * 16 + (lane & 15);
                uint32_t addr = dbase + (uint32_t)(r * 128)
                              + ((kcol + a_lc) ^ (uint32_t)((r & 7) * 16));
                ldsm4(af[mt], addr);
            }
            uint32_t bfr[8][2];
#pragma unroll
            for (int jq = 0; jq < 4; ++jq) {
                int r = wn * 64 + jq * 16 + (lane & 7) + b_r8;
                uint32_t addr = dbase + 8192u + (uint32_t)(r * 128)
                              + ((kcol + b_lc) ^ (uint32_t)((r & 7) * 16));
                uint32_t t4[4];
                ldsm4(t4, addr);
                bfr[jq * 2][0] = t4[0];     bfr[jq * 2][1] = t4[1];
                bfr[jq * 2 + 1][0] = t4[2]; bfr[jq * 2 + 1][1] = t4[3];
            }
#pragma unroll
            for (int jt = 0; jt < 8; ++jt)
#pragma unroll
                for (int mt = 0; mt < 2; ++mt)
                    mma16816h(acc[mt][jt], af[mt], bfr[jt][0], bfr[jt][1]);
        }
        __syncthreads();
    }

    // ---------------- epilogue ----------------
    if (!LSTM) {
#pragma unroll
        for (int mt = 0; mt < 2; mt++) {
            int r = bm + wm * 32 + mt * 16 + (lane >> 2);
#pragma unroll
            for (int jt = 0; jt < 8; jt++) {
                int cix = bn + wn * 64 + jt * 8 + (lane & 3) * 2;
                float* o = outZ + (size_t)r * NG + cix;
                o[0] = acc[mt][jt][0]; o[1] = acc[mt][jt][1];
                o += (size_t)8 * NG;
                o[0] = acc[mt][jt][2]; o[1] = acc[mt][jt][3];
            }
        }
    } else {
        // all-lane LSTM epilogue: even lane -> row rA, odd lane -> rA+8.
        const int par = lane & 1;
#pragma unroll
        for (int mt = 0; mt < 2; mt++) {
            const int rA = bm + wm * 32 + mt * 16 + (lane >> 2);
            const int r  = rA + par * 8;
#pragma unroll
            for (int jt = 0; jt < 8; jt++) {
                const int cix = bn + wn * 64 + jt * 8 + (lane & 3) * 2;
                float z0 = acc[mt][jt][0] + bias[cix];
                float z1 = acc[mt][jt][1] + bias[cix + 1];
                float z2 = acc[mt][jt][2] + bias[cix];
                float z3 = acc[mt][jt][3] + bias[cix + 1];
                if (pre) {
                    z0 += pre[(size_t)rA * preStride + cix];
                    z1 += pre[(size_t)rA * preStride + cix + 1];
                    z2 += pre[(size_t)(rA + 8) * preStride + cix];
                    z3 += pre[(size_t)(rA + 8) * preStride + cix + 1];
                }
                float s0 = par ? z0 : z2;
                float s1 = par ? z1 : z3;
                float q0 = __shfl_xor_sync(0xffffffffu, s0, 1);
                float q1 = __shfl_xor_sync(0xffffffffu, s1, 1);
                float zi = par ? q0 : z0;
                float zf = par ? q1 : z1;
                float zg = par ? z2 : q0;
                float zo = par ? z3 : q1;
                const int j = cix >> 2;
                const size_t si = (size_t)r * NH + j;
                float ig = sigf(zi), fg = sigf(zf), og = sigf(zo);
                float gg = tanhff(zg);
                float cn = fg * cState[si] + ig * gg;
                float h = og * tanhff(cn);
                cState[si] = cn;
                __half hh = __float2half(h);
                hOut[si] = hh;
                if (yOut) yOut[(size_t)r * yStride + j] = hh;
                if (yF32) yF32[(size_t)r * yStride + j] = h;
            }
        }
    }
}

// ---------------- final dense ----------------
__global__ void k_dense(const float* __restrict__ w, const float* __restrict__ b,
                        float* __restrict__ out) {
    int r = blockIdx.x * 8 + (threadIdx.x >> 5);
    int lane = threadIdx.x & 31;
    const float* row = g_D1 + (size_t)r * NH;
    float s = 0.0f;
#pragma unroll
    for (int k = lane; k < NH; k += 32) s += row[k] * w[k];
#pragma unroll
    for (int o = 16; o; o >>= 1) s += __shfl_xor_sync(0xffffffffu, s, o);
    if (lane == 0) out[r] = s + b[0];
}

// ---------------- host ----------------
extern "C" void kernel_launch(void* const* d_in, const int* in_sizes, int n_in,
                              void* d_out, int out_size) {
    (void)in_sizes; (void)n_in; (void)out_size;
    const float* x      = (const float*)d_in[0];
    const float* eW0    = (const float*)d_in[2];
    const float* eU0    = (const float*)d_in[3];
    const float* eb0    = (const float*)d_in[4];
    const float* eW1    = (const float*)d_in[5];
    const float* eU1    = (const float*)d_in[6];
    const float* eb1    = (const float*)d_in[7];
    const float* dU0    = (const float*)d_in[9];
    const float* db0    = (const float*)d_in[10];
    const float* dW1    = (const float*)d_in[11];
    const float* dU1    = (const float*)d_in[12];
    const float* db1    = (const float*)d_in[13];
    const float* denseW = (const float*)d_in[14];
    const float* denseb = (const float*)d_in[15];

    cudaFuncSetAttribute(k_gemm1<true>,  cudaFuncAttributeMaxDynamicSharedMemorySize, SMEM_DYN);
    cudaFuncSetAttribute(k_gemm1<false>, cudaFuncAttributeMaxDynamicSharedMemorySize, SMEM_DYN);

    void *pZ, *pX, *pY, *pD1, *pA, *pB, *pCA, *pCB, *pW, *pBs;
    cudaGetSymbolAddress(&pZ, g_Z);
    cudaGetSymbolAddress(&pX, g_X);
    cudaGetSymbolAddress(&pY, g_Y);
    cudaGetSymbolAddress(&pD1, g_D1);
    cudaGetSymbolAddress(&pA, g_hA);
    cudaGetSymbolAddress(&pB, g_hB);
    cudaGetSymbolAddress(&pCA, g_cA);  cudaGetSymbolAddress(&pCB, g_cB);
    cudaGetSymbolAddress(&pW, g_WT);
    cudaGetSymbolAddress(&pBs, g_bias);

    float* Z = (float*)pZ;
    __half* X = (__half*)pX;
    __half* Y = (__half*)pY;
    float* D1 = (float*)pD1;
    __half* hA[2] = {(__half*)pA, (__half*)pA + NB * NH};
    __half* hB[2] = {(__half*)pB, (__half*)pB + NB * NH};
    float* cA = (float*)pCA; float* cB = (float*)pCB;
    __half* W = (__half*)pW;
    float* Bias = (float*)pBs;

    // --- prep: 2 launches ---
    {
        long long wtot = 2048LL * 128 + 6LL * 2048 * 512;
        k_prep_weights<<<(int)((wtot + 255) / 256), 256>>>(eW0, eU0, eW1, eU1, dU0, dW1, dU1);
        long long mtot = 4LL * NG + (long long)NB * NT * 128 + (long long)NB * NH;
        k_prep_misc<<<(int)((mtot + 255) / 256), 256>>>(x, eb0, eb1, db0, db1);
    }

    const dim3 blk(256);
    const dim3 gStep(NB / 64, 8);   // 128 CTAs

    // --- encoder L0: precompute x@eW0, then 64 recurrent steps ---
    k_gemm1<false><<<dim3(NB * NT / 64, 8), blk, SMEM_DYN>>>(
        X, 128, W + O_eW0, 128, 2, Z,
        nullptr, 0, nullptr, nullptr, nullptr, nullptr, 0, nullptr);
    for (int t = 0; t < NT; t++) {
        k_gemm1<true><<<gStep, blk, SMEM_DYN>>>(
            hA[t & 1], NH, W + O_eU0, NH, 8, nullptr,
            Z + (size_t)t * NG, (long long)NT * NG, Bias + 0 * NG, cA,
            hA[(t + 1) & 1],
            Y + (size_t)t * NH, (long long)NT * NH, nullptr);
    }
    // --- encoder L1: precompute y0@eW1, then 64 steps ---
    k_gemm1<false><<<dim3(NB * NT / 64, 8), blk, SMEM_DYN>>>(
        Y, NH, W + O_eW1, NH, 8, Z,
        nullptr, 0, nullptr, nullptr, nullptr, nullptr, 0, nullptr);
    for (int t = 0; t < NT; t++) {
        k_gemm1<true><<<gStep, blk, SMEM_DYN>>>(
            hB[t & 1], NH, W + O_eU1, NH, 8, nullptr,
            Z + (size_t)t * NG, (long long)NT * NG, Bias + 1 * NG, cB,
            hB[(t + 1) & 1],
            nullptr, 0, nullptr);
    }
    // --- decoder L0: zero input; continues from enc-L0 final state ---
    for (int t = 0; t < NSEG; t++) {
        k_gemm1<true><<<gStep, blk, SMEM_DYN>>>(
            hA[t & 1], NH, W + O_dU0, NH, 8, nullptr,
            nullptr, 0, Bias + 2 * NG, cA,
            hA[(t + 1) & 1],
            Y + (size_t)t * NH, (long long)NSEG * NH, nullptr);
    }
    // --- decoder L1: precompute d0@dW1, then 32 steps, emit fp32 d1 ---
    k_gemm1<false><<<dim3(NB * NSEG / 64, 8), blk, SMEM_DYN>>>(
        Y, NH, W + O_dW1, NH, 8, Z,
        nullptr, 0, nullptr, nullptr, nullptr, nullptr, 0, nullptr);
    for (int t = 0; t < NSEG; t++) {
        k_gemm1<true><<<gStep, blk, SMEM_DYN>>>(
            hB[t & 1], NH, W + O_dU1, NH, 8, nullptr,
            Z + (size_t)t * NG, (long long)NSEG * NG, Bias + 3 * NG, cB,
            hB[(t + 1) & 1],
            nullptr, (long long)NSEG * NH, D1 + (size_t)t * NH);
    }
    // --- final dense ---
    k_dense<<<NB * NSEG / 8, 256>>>(denseW, denseb, (float*)d_out);
}